// round 4
// baseline (speedup 1.0000x reference)
#include <cuda_runtime.h>
#include <math.h>

// Problem constants (fixed by the reference).
#define BZ   2
#define SQ   2048
#define DM   1024
#define NH   16
#define HD   64
#define MTOT (BZ * SQ)   // 4096

// ---------------------------------------------------------------------------
// Scratch (device globals: no allocation allowed in kernel_launch)
// ---------------------------------------------------------------------------
__device__ float g_Q[BZ * NH * SQ * HD];    // [B,H,S,Hd]
__device__ float g_K[BZ * NH * SQ * HD];
__device__ float g_V[BZ * NH * SQ * HD];
__device__ float g_ctx[BZ * SQ * DM];       // [B,S,D]

// ---------------------------------------------------------------------------
// Tiled SGEMM:  Y[m,n] = sum_k X[m,k] * W[n,k] + bias[n]
// X: [M,K] row-major, W: [N,K] row-major (nn.Linear weight), K = DM = 1024.
// HEAD_LAYOUT=1: write to [B,H,S,Hd] scratch;  =0: write row-major [M,N].
// BM=BN=128, BK=8, 256 threads, 8x8 per thread.
// ---------------------------------------------------------------------------
#define GBM 128
#define GBN 128
#define GBK 8
#define GTM 8
#define GTN 8

template <int HEAD_LAYOUT>
__global__ __launch_bounds__(256, 2)
void proj_kernel(const float* __restrict__ X, const float* __restrict__ W,
                 const float* __restrict__ bias, float* __restrict__ Y,
                 int M, int N, int K)
{
    __shared__ float As[GBK][GBM + 4];
    __shared__ float Bs[GBK][GBN + 4];

    const int tid = threadIdx.x;
    const int tx  = tid & 15;        // 0..15  -> N direction
    const int ty  = tid >> 4;        // 0..15  -> M direction

    const int row_ld = tid >> 1;           // 0..127
    const int k4     = (tid & 1) * 4;      // 0 or 4

    const float* Xp = X + (size_t)(blockIdx.y * GBM + row_ld) * K + k4;
    const float* Wp = W + (size_t)(blockIdx.x * GBN + row_ld) * K + k4;

    float acc[GTM][GTN];
#pragma unroll
    for (int i = 0; i < GTM; i++)
#pragma unroll
        for (int j = 0; j < GTN; j++) acc[i][j] = 0.f;

    for (int k0 = 0; k0 < K; k0 += GBK) {
        float4 a4 = *(const float4*)(Xp + k0);
        float4 b4 = *(const float4*)(Wp + k0);
        As[k4 + 0][row_ld] = a4.x; As[k4 + 1][row_ld] = a4.y;
        As[k4 + 2][row_ld] = a4.z; As[k4 + 3][row_ld] = a4.w;
        Bs[k4 + 0][row_ld] = b4.x; Bs[k4 + 1][row_ld] = b4.y;
        Bs[k4 + 2][row_ld] = b4.z; Bs[k4 + 3][row_ld] = b4.w;
        __syncthreads();

#pragma unroll
        for (int k = 0; k < GBK; k++) {
            float4 a0 = *(const float4*)&As[k][ty * GTM];
            float4 a1 = *(const float4*)&As[k][ty * GTM + 4];
            float4 b0 = *(const float4*)&Bs[k][tx * GTN];
            float4 b1 = *(const float4*)&Bs[k][tx * GTN + 4];
            float a[GTM] = {a0.x, a0.y, a0.z, a0.w, a1.x, a1.y, a1.z, a1.w};
            float b[GTN] = {b0.x, b0.y, b0.z, b0.w, b1.x, b1.y, b1.z, b1.w};
#pragma unroll
            for (int i = 0; i < GTM; i++)
#pragma unroll
                for (int j = 0; j < GTN; j++)
                    acc[i][j] = fmaf(a[i], b[j], acc[i][j]);
        }
        __syncthreads();
    }

    // Epilogue: bias + layout
#pragma unroll
    for (int i = 0; i < GTM; i++) {
        int m = blockIdx.y * GBM + ty * GTM + i;
#pragma unroll
        for (int j = 0; j < GTN; j++) {
            int n = blockIdx.x * GBN + tx * GTN + j;
            float v = acc[i][j] + bias[n];
            if (HEAD_LAYOUT) {
                int b  = m / SQ, s  = m % SQ;
                int h  = n / HD, hd = n % HD;
                Y[(((size_t)b * NH + h) * SQ + s) * HD + hd] = v;
            } else {
                Y[(size_t)m * N + n] = v;
            }
        }
    }
}

// ---------------------------------------------------------------------------
// Flash attention: per (b*H + h, query-tile of 64 rows).
// Online softmax over 32-key tiles. Hd = 64.
// 256 threads = 8 warps; warp w owns query rows w*8..w*8+7.
// Lane owns key-col c = lane (tile width 32) and output dims {lane, lane+32}.
// ---------------------------------------------------------------------------
#define ABM 64
#define ABN 32
#define QSS 68   // Qs row stride (floats): 16B-aligned rows, conflict-free
#define KSS 68   // Ks/Vs row stride
#define PSS 36   // Ps row stride

__global__ __launch_bounds__(256)
void attn_kernel(const float* __restrict__ Q, const float* __restrict__ K,
                 const float* __restrict__ V, float* __restrict__ ctx)
{
    __shared__ float Qs[ABM * QSS];   // 17408 B
    __shared__ float Ks[ABN * KSS];   //  8704 B
    __shared__ float Vs[ABN * KSS];   //  8704 B
    __shared__ float Ps[ABM * PSS];   //  9216 B   (total 44032 B)

    const int bh  = blockIdx.x;               // b*NH + h
    const int m0  = blockIdx.y * ABM;         // first query row
    const int tid = threadIdx.x;
    const int warp = tid >> 5, lane = tid & 31;
    const int r0 = warp * 8;

    const float* Qb = Q + (size_t)bh * SQ * HD;
    const float* Kb = K + (size_t)bh * SQ * HD;
    const float* Vb = V + (size_t)bh * SQ * HD;

    // Load the 64x64 Q tile once.
    for (int i = tid * 4; i < ABM * HD; i += 256 * 4) {
        int r = i >> 6, c = i & 63;
        float4 q = *(const float4*)(Qb + (size_t)(m0 + r) * HD + c);
        Qs[r * QSS + c + 0] = q.x; Qs[r * QSS + c + 1] = q.y;
        Qs[r * QSS + c + 2] = q.z; Qs[r * QSS + c + 3] = q.w;
    }

    float mi[8], li[8], acc0[8], acc1[8];
#pragma unroll
    for (int r = 0; r < 8; r++) { mi[r] = -1e30f; li[r] = 0.f; acc0[r] = 0.f; acc1[r] = 0.f; }

    const float sm_scale = 0.125f;  // 1/sqrt(64)

    for (int kt = 0; kt < SQ; kt += ABN) {
        __syncthreads();   // previous iteration's PV reads finished
        // Fill K/V tiles (32x64 each), coalesced float4.
        for (int i = tid * 4; i < ABN * HD; i += 256 * 4) {
            int c = i >> 6, k = i & 63;
            float4 kv = *(const float4*)(Kb + (size_t)(kt + c) * HD + k);
            Ks[c * KSS + k + 0] = kv.x; Ks[c * KSS + k + 1] = kv.y;
            Ks[c * KSS + k + 2] = kv.z; Ks[c * KSS + k + 3] = kv.w;
            float4 vv = *(const float4*)(Vb + (size_t)(kt + c) * HD + k);
            Vs[c * KSS + k + 0] = vv.x; Vs[c * KSS + k + 1] = vv.y;
            Vs[c * KSS + k + 2] = vv.z; Vs[c * KSS + k + 3] = vv.w;
        }
        __syncthreads();

        // s[r] = Q[r0+r,:] . K[lane,:]
        float s[8];
#pragma unroll
        for (int r = 0; r < 8; r++) s[r] = 0.f;
#pragma unroll
        for (int k4 = 0; k4 < HD; k4 += 4) {
            float4 kv = *(const float4*)&Ks[lane * KSS + k4];
#pragma unroll
            for (int r = 0; r < 8; r++) {
                float4 q = *(const float4*)&Qs[(r0 + r) * QSS + k4];
                s[r] += q.x * kv.x + q.y * kv.y + q.z * kv.z + q.w * kv.w;
            }
        }

        // Online softmax per row (reduce across 32 lanes).
#pragma unroll
        for (int r = 0; r < 8; r++) {
            float sv = s[r] * sm_scale;
            float rowmax = sv;
#pragma unroll
            for (int o = 16; o > 0; o >>= 1)
                rowmax = fmaxf(rowmax, __shfl_xor_sync(0xffffffffu, rowmax, o));
            float nm   = fmaxf(mi[r], rowmax);
            float p    = __expf(sv - nm);
            float corr = __expf(mi[r] - nm);
            float rs = p;
#pragma unroll
            for (int o = 16; o > 0; o >>= 1)
                rs += __shfl_xor_sync(0xffffffffu, rs, o);
            li[r] = li[r] * corr + rs;
            mi[r] = nm;
            acc0[r] *= corr;
            acc1[r] *= corr;
            Ps[(r0 + r) * PSS + lane] = p;
        }
        __syncwarp();   // Ps rows are warp-private

        // acc[r,d] += sum_c P[r,c] * V[c,d],  d in {lane, lane+32}
#pragma unroll
        for (int c4 = 0; c4 < ABN; c4 += 4) {
            float va0 = Vs[(c4 + 0) * KSS + lane];
            float va1 = Vs[(c4 + 1) * KSS + lane];
            float va2 = Vs[(c4 + 2) * KSS + lane];
            float va3 = Vs[(c4 + 3) * KSS + lane];
            float vb0 = Vs[(c4 + 0) * KSS + lane + 32];
            float vb1 = Vs[(c4 + 1) * KSS + lane + 32];
            float vb2 = Vs[(c4 + 2) * KSS + lane + 32];
            float vb3 = Vs[(c4 + 3) * KSS + lane + 32];
#pragma unroll
            for (int r = 0; r < 8; r++) {
                float4 p4 = *(const float4*)&Ps[(r0 + r) * PSS + c4];
                acc0[r] += p4.x * va0 + p4.y * va1 + p4.z * va2 + p4.w * va3;
                acc1[r] += p4.x * vb0 + p4.y * vb1 + p4.z * vb2 + p4.w * vb3;
            }
        }
    }

    // Epilogue: normalize and write ctx in [B,S,D] merged-head layout.
    const int b = bh / NH, h = bh % NH;
#pragma unroll
    for (int r = 0; r < 8; r++) {
        float inv = 1.f / li[r];
        int srow = m0 + r0 + r;
        float* op = ctx + ((size_t)b * SQ + srow) * DM + h * HD;
        op[lane]      = acc0[r] * inv;
        op[lane + 32] = acc1[r] * inv;
    }
}

// ---------------------------------------------------------------------------
// Launch
// ---------------------------------------------------------------------------
extern "C" void kernel_launch(void* const* d_in, const int* in_sizes, int n_in,
                              void* d_out, int out_size)
{
    const float* query = (const float*)d_in[0];
    const float* key   = (const float*)d_in[1];
    const float* value = (const float*)d_in[2];
    const float* Wq = (const float*)d_in[3];
    const float* bq = (const float*)d_in[4];
    const float* Wk = (const float*)d_in[5];
    const float* bk = (const float*)d_in[6];
    const float* Wv = (const float*)d_in[7];
    const float* bv = (const float*)d_in[8];
    const float* Wo = (const float*)d_in[9];
    const float* bo = (const float*)d_in[10];
    float* out = (float*)d_out;

    float *pQ, *pK, *pV, *pC;
    cudaGetSymbolAddress((void**)&pQ, g_Q);
    cudaGetSymbolAddress((void**)&pK, g_K);
    cudaGetSymbolAddress((void**)&pV, g_V);
    cudaGetSymbolAddress((void**)&pC, g_ctx);

    dim3 pg(DM / GBN, MTOT / GBM);   // (8, 32)
    proj_kernel<1><<<pg, 256>>>(query, Wq, bq, pQ, MTOT, DM, DM);
    proj_kernel<1><<<pg, 256>>>(key,   Wk, bk, pK, MTOT, DM, DM);
    proj_kernel<1><<<pg, 256>>>(value, Wv, bv, pV, MTOT, DM, DM);

    dim3 ag(BZ * NH, SQ / ABM);      // (32, 32)
    attn_kernel<<<ag, 256>>>(pQ, pK, pV, pC);

    proj_kernel<0><<<pg, 256>>>(pC, Wo, bo, out, MTOT, DM, DM);
}

// round 5
// speedup vs baseline: 1.2619x; 1.2619x over previous
#include <cuda_runtime.h>
#include <math.h>

// Problem constants (fixed by the reference).
#define BZ   2
#define SQ   2048
#define DM   1024
#define NH   16
#define HD   64
#define MTOT (BZ * SQ)   // 4096

typedef unsigned long long u64;

// ---------------------------------------------------------------------------
// Packed f32x2 helpers (Blackwell FFMA2 path — ptxas won't emit these itself)
// ---------------------------------------------------------------------------
__device__ __forceinline__ u64 dup2(float x) {
    u64 d; unsigned xi = __float_as_uint(x);
    asm("mov.b64 %0, {%1,%1};" : "=l"(d) : "r"(xi));
    return d;
}
__device__ __forceinline__ u64 pk2(float lo, float hi) {
    u64 d;
    asm("mov.b64 %0, {%1,%2};" : "=l"(d)
        : "r"(__float_as_uint(lo)), "r"(__float_as_uint(hi)));
    return d;
}
__device__ __forceinline__ void up2(u64 v, float& lo, float& hi) {
    unsigned a, b;
    asm("mov.b64 {%0,%1}, %2;" : "=r"(a), "=r"(b) : "l"(v));
    lo = __uint_as_float(a); hi = __uint_as_float(b);
}
__device__ __forceinline__ u64 ff2(u64 a, u64 b, u64 c) {
    u64 d;
    asm("fma.rn.f32x2 %0, %1, %2, %3;" : "=l"(d) : "l"(a), "l"(b), "l"(c));
    return d;
}
__device__ __forceinline__ u64 fm2(u64 a, u64 b) {
    u64 d;
    asm("mul.rn.f32x2 %0, %1, %2;" : "=l"(d) : "l"(a), "l"(b));
    return d;
}

// ---------------------------------------------------------------------------
// Scratch (device globals: no allocation allowed in kernel_launch)
// ---------------------------------------------------------------------------
__device__ float g_Q[BZ * NH * SQ * HD];    // [B,H,S,Hd]
__device__ float g_K[BZ * NH * SQ * HD];
__device__ float g_V[BZ * NH * SQ * HD];
__device__ float g_ctx[BZ * SQ * DM];       // [B,S,D]

// ---------------------------------------------------------------------------
// proj2: Y[m,n] = sum_k X[m,k] * W[n,k] + bias[n], K = 1024.
// 128x128 tile, BK=8 double-buffered, 256 threads, 8 rows x 8 cols / thread,
// row-pair f32x2 accumulators. HEAD_LAYOUT=1 -> [B,H,S,Hd] scatter.
// ---------------------------------------------------------------------------
#define PSTR 132

template <int HEAD_LAYOUT>
__global__ __launch_bounds__(256, 2)
void proj2_kernel(const float* __restrict__ X, const float* __restrict__ W,
                  const float* __restrict__ bias, float* __restrict__ Y)
{
    __shared__ float As[2][8][PSTR];
    __shared__ float Bs[2][8][PSTR];

    const int tid = threadIdx.x;
    const int tx = tid & 15;          // 16 -> N (cols 4tx and 64+4tx)
    const int ty = tid >> 4;          // 16 -> M (rows 8ty..8ty+7)

    const int row_ld = tid >> 1;            // 0..127
    const int k4     = (tid & 1) * 4;       // 0 or 4

    const float* Xp = X + (size_t)(blockIdx.y * 128 + row_ld) * 1024 + k4;
    const float* Wp = W + (size_t)(blockIdx.x * 128 + row_ld) * 1024 + k4;

    u64 acc[4][8];
#pragma unroll
    for (int i = 0; i < 4; i++)
#pragma unroll
        for (int j = 0; j < 8; j++) acc[i][j] = 0ull;

    // prologue: stage 0
    {
        float4 a4 = *(const float4*)Xp;
        float4 b4 = *(const float4*)Wp;
        As[0][k4 + 0][row_ld] = a4.x; As[0][k4 + 1][row_ld] = a4.y;
        As[0][k4 + 2][row_ld] = a4.z; As[0][k4 + 3][row_ld] = a4.w;
        Bs[0][k4 + 0][row_ld] = b4.x; Bs[0][k4 + 1][row_ld] = b4.y;
        Bs[0][k4 + 2][row_ld] = b4.z; Bs[0][k4 + 3][row_ld] = b4.w;
    }
    __syncthreads();

    for (int kt = 0; kt < 128; kt++) {
        const int cur = kt & 1;
        float4 na, nb;
        if (kt < 127) {
            na = *(const float4*)(Xp + (kt + 1) * 8);
            nb = *(const float4*)(Wp + (kt + 1) * 8);
        }
#pragma unroll
        for (int k = 0; k < 8; k++) {
            ulonglong2 aa = *(const ulonglong2*)&As[cur][k][8 * ty];
            ulonglong2 ab = *(const ulonglong2*)&As[cur][k][8 * ty + 4];
            float4 b0 = *(const float4*)&Bs[cur][k][4 * tx];
            float4 b1 = *(const float4*)&Bs[cur][k][64 + 4 * tx];
            u64 a2[4] = {aa.x, aa.y, ab.x, ab.y};
            u64 bd[8] = {dup2(b0.x), dup2(b0.y), dup2(b0.z), dup2(b0.w),
                         dup2(b1.x), dup2(b1.y), dup2(b1.z), dup2(b1.w)};
#pragma unroll
            for (int i = 0; i < 4; i++)
#pragma unroll
                for (int j = 0; j < 8; j++)
                    acc[i][j] = ff2(a2[i], bd[j], acc[i][j]);
        }
        if (kt < 127) {
            const int nxt = cur ^ 1;
            As[nxt][k4 + 0][row_ld] = na.x; As[nxt][k4 + 1][row_ld] = na.y;
            As[nxt][k4 + 2][row_ld] = na.z; As[nxt][k4 + 3][row_ld] = na.w;
            Bs[nxt][k4 + 0][row_ld] = nb.x; Bs[nxt][k4 + 1][row_ld] = nb.y;
            Bs[nxt][k4 + 2][row_ld] = nb.z; Bs[nxt][k4 + 3][row_ld] = nb.w;
        }
        __syncthreads();
    }

    // Epilogue
#pragma unroll
    for (int i = 0; i < 4; i++) {
        int m = blockIdx.y * 128 + 8 * ty + 2 * i;
#pragma unroll
        for (int j = 0; j < 8; j++) {
            float lo, hi; up2(acc[i][j], lo, hi);
            int n = blockIdx.x * 128 + (j < 4 ? 4 * tx + j : 64 + 4 * tx + (j - 4));
            float bj = bias[n];
            float v0 = lo + bj, v1 = hi + bj;
            if (HEAD_LAYOUT) {
                int b = m / SQ, s = m % SQ;
                int h = n / HD, hd = n % HD;
                size_t base = (((size_t)b * NH + h) * SQ + s) * HD + hd;
                Y[base] = v0;
                Y[base + HD] = v1;   // next s row: +1 row in [S,Hd] = +HD
            } else {
                Y[(size_t)m * DM + n] = v0;
                Y[(size_t)(m + 1) * DM + n] = v1;
            }
        }
    }
}

// ---------------------------------------------------------------------------
// attn2: flash attention, 128 query rows / block, 64-key tiles, f32x2 math.
// 256 threads as 16x16 grid: thread (tx,ty): rows 8ty..+7, cols 4tx..+3.
// Q/K/P in k-major smem with XOR-block swizzle; V row-major.
// ---------------------------------------------------------------------------
#define AM 128
#define AN 64
#define QS 132   // Qst stride (floats)
#define KS 68
#define VSW 68
#define PS 132

#define ATTN_SMEM_FLOATS (64*QS + 64*KS + 64*VSW + 64*PS)   // 25600
#define ATTN_SMEM_BYTES  (ATTN_SMEM_FLOATS * 4)             // 102400

__global__ __launch_bounds__(256, 2)
void attn2_kernel(const float* __restrict__ Q, const float* __restrict__ K,
                  const float* __restrict__ V, float* __restrict__ ctx)
{
    extern __shared__ float sm[];
    float* Qst = sm;                    // [k=64][QS]  (swizzled blocks of 4 rows)
    float* Kst = sm + 64 * QS;          // [k=64][KS]  (swizzled blocks of 4 cols)
    float* Vs  = Kst + 64 * KS;         // [c=64][VSW]
    float* Pst = Vs + 64 * VSW;         // [c=64][PS]  (swizzled blocks of 4 rows)

    const int bh  = blockIdx.x;               // b*NH + h
    const int m0  = blockIdx.y * AM;
    const int tid = threadIdx.x;
    const int tx = tid & 15, ty = tid >> 4;

    const float* Qb = Q + (size_t)bh * SQ * HD;
    const float* Kb = K + (size_t)bh * SQ * HD;
    const float* Vb = V + (size_t)bh * SQ * HD;

    // ---- load Q tile (once), pre-scaled by 1/sqrt(Hd), transposed+swizzled ----
    {
        const float4* Qg = (const float4*)(Qb + (size_t)m0 * HD);
        for (int i4 = tid; i4 < AM * HD / 4; i4 += 256) {
            int m = i4 >> 4, d4 = (i4 & 15) << 2;
            float4 q = Qg[i4];
            float v[4] = {q.x * 0.125f, q.y * 0.125f, q.z * 0.125f, q.w * 0.125f};
#pragma unroll
            for (int u = 0; u < 4; u++) {
                int k = d4 + u;
                Qst[k * QS + ((((m >> 2) ^ (k & 31)) << 2) | (m & 3))] = v[u];
            }
        }
    }

    u64 o2[4][4];
#pragma unroll
    for (int i = 0; i < 4; i++)
#pragma unroll
        for (int j = 0; j < 4; j++) o2[i][j] = 0ull;
    float mi[8], li[8];
#pragma unroll
    for (int r = 0; r < 8; r++) { mi[r] = -1e30f; li[r] = 0.f; }

    for (int kt0 = 0; kt0 < SQ; kt0 += AN) {
        __syncthreads();   // prev tile fully consumed (QK read Kst, PV read Vs/Pst)

        // ---- fill K (transposed+swizzled) and V (row-major) ----
        {
            const float4* Kg = (const float4*)(Kb + (size_t)kt0 * HD);
            const float4* Vg = (const float4*)(Vb + (size_t)kt0 * HD);
            for (int i4 = tid; i4 < AN * HD / 4; i4 += 256) {
                int c = i4 >> 4, d4 = (i4 & 15) << 2;
                float4 kv = Kg[i4];
                float kvv[4] = {kv.x, kv.y, kv.z, kv.w};
#pragma unroll
                for (int u = 0; u < 4; u++) {
                    int k = d4 + u;
                    Kst[k * KS + ((((c >> 2) ^ (k & 15)) << 2) | (c & 3))] = kvv[u];
                }
                float4 vv = Vg[i4];
                *(float4*)(Vs + c * VSW + d4) = vv;
            }
        }
        __syncthreads();

        // ---- QK^T: S[8 rows][4 cols] in f32x2 row pairs ----
        u64 s2[4][4];
#pragma unroll
        for (int i = 0; i < 4; i++)
#pragma unroll
            for (int j = 0; j < 4; j++) s2[i][j] = 0ull;

#pragma unroll 8
        for (int k = 0; k < 64; k++) {
            const float* qr = Qst + k * QS;
            ulonglong2 qa = *(const ulonglong2*)(qr + (((2 * ty) ^ (k & 31)) << 2));
            ulonglong2 qb = *(const ulonglong2*)(qr + (((2 * ty + 1) ^ (k & 31)) << 2));
            float4 kk = *(const float4*)(Kst + k * KS + ((tx ^ (k & 15)) << 2));
            u64 q2[4] = {qa.x, qa.y, qb.x, qb.y};
            u64 kd[4] = {dup2(kk.x), dup2(kk.y), dup2(kk.z), dup2(kk.w)};
#pragma unroll
            for (int i = 0; i < 4; i++)
#pragma unroll
                for (int j = 0; j < 4; j++)
                    s2[i][j] = ff2(q2[i], kd[j], s2[i][j]);
        }

        // ---- online softmax (row groups are half-warps: width-16 shuffles) ----
        float s[8][4];
#pragma unroll
        for (int i = 0; i < 4; i++)
#pragma unroll
            for (int j = 0; j < 4; j++) up2(s2[i][j], s[2 * i][j], s[2 * i + 1][j]);

        float corr[8];
#pragma unroll
        for (int r = 0; r < 8; r++) {
            float mx = fmaxf(fmaxf(s[r][0], s[r][1]), fmaxf(s[r][2], s[r][3]));
#pragma unroll
            for (int o = 8; o > 0; o >>= 1)
                mx = fmaxf(mx, __shfl_xor_sync(0xffffffffu, mx, o, 16));
            float mn = fmaxf(mi[r], mx);
            corr[r] = __expf(mi[r] - mn);
            mi[r] = mn;
            float ps = 0.f;
#pragma unroll
            for (int j = 0; j < 4; j++) {
                float p = __expf(s[r][j] - mn);
                s[r][j] = p; ps += p;
            }
            li[r] = li[r] * corr[r] + ps;   // lane-partial sum over own 4 cols
        }
#pragma unroll
        for (int i = 0; i < 4; i++) {
            u64 c2 = pk2(corr[2 * i], corr[2 * i + 1]);
#pragma unroll
            for (int j = 0; j < 4; j++) o2[i][j] = fm2(o2[i][j], c2);
        }

        // ---- store P transposed+swizzled: Pst[c][r] ----
#pragma unroll
        for (int j = 0; j < 4; j++) {
            int c = 4 * tx + j;
            float* pc = Pst + c * PS;
#pragma unroll
            for (int o = 0; o < 2; o++) {
                int blk = (2 * ty + o) ^ (c & 31);
                float4 pv = make_float4(s[4 * o + 0][j], s[4 * o + 1][j],
                                        s[4 * o + 2][j], s[4 * o + 3][j]);
                *(float4*)(pc + (blk << 2)) = pv;
            }
        }
        __syncwarp();   // producers/consumers of these P rows share a half-warp

        // ---- PV: out[8 rows][4 dims] += P * V ----
#pragma unroll 8
        for (int c = 0; c < 64; c++) {
            const float* pc = Pst + c * PS;
            ulonglong2 pa = *(const ulonglong2*)(pc + (((2 * ty) ^ (c & 31)) << 2));
            ulonglong2 pb = *(const ulonglong2*)(pc + (((2 * ty + 1) ^ (c & 31)) << 2));
            float4 vv = *(const float4*)(Vs + c * VSW + 4 * tx);
            u64 p2[4] = {pa.x, pa.y, pb.x, pb.y};
            u64 vd[4] = {dup2(vv.x), dup2(vv.y), dup2(vv.z), dup2(vv.w)};
#pragma unroll
            for (int i = 0; i < 4; i++)
#pragma unroll
                for (int j = 0; j < 4; j++)
                    o2[i][j] = ff2(p2[i], vd[j], o2[i][j]);
        }
    }

    // ---- final li reduction across the 16 col-owners, then write ctx ----
#pragma unroll
    for (int r = 0; r < 8; r++) {
#pragma unroll
        for (int o = 8; o > 0; o >>= 1)
            li[r] += __shfl_xor_sync(0xffffffffu, li[r], o, 16);
    }
    const int b = bh >> 4, h = bh & 15;
#pragma unroll
    for (int i = 0; i < 4; i++) {
        float lo[4], hi[4];
#pragma unroll
        for (int j = 0; j < 4; j++) up2(o2[i][j], lo[j], hi[j]);
        int rg = m0 + 8 * ty + 2 * i;
        float inv0 = 1.f / li[2 * i], inv1 = 1.f / li[2 * i + 1];
        float4 w0 = make_float4(lo[0] * inv0, lo[1] * inv0, lo[2] * inv0, lo[3] * inv0);
        float4 w1 = make_float4(hi[0] * inv1, hi[1] * inv1, hi[2] * inv1, hi[3] * inv1);
        *(float4*)(ctx + ((size_t)b * SQ + rg) * DM + h * HD + 4 * tx) = w0;
        *(float4*)(ctx + ((size_t)b * SQ + rg + 1) * DM + h * HD + 4 * tx) = w1;
    }
}

// ---------------------------------------------------------------------------
// Launch
// ---------------------------------------------------------------------------
extern "C" void kernel_launch(void* const* d_in, const int* in_sizes, int n_in,
                              void* d_out, int out_size)
{
    const float* query = (const float*)d_in[0];
    const float* key   = (const float*)d_in[1];
    const float* value = (const float*)d_in[2];
    const float* Wq = (const float*)d_in[3];
    const float* bq = (const float*)d_in[4];
    const float* Wk = (const float*)d_in[5];
    const float* bk = (const float*)d_in[6];
    const float* Wv = (const float*)d_in[7];
    const float* bv = (const float*)d_in[8];
    const float* Wo = (const float*)d_in[9];
    const float* bo = (const float*)d_in[10];
    float* out = (float*)d_out;

    float *pQ, *pK, *pV, *pC;
    cudaGetSymbolAddress((void**)&pQ, g_Q);
    cudaGetSymbolAddress((void**)&pK, g_K);
    cudaGetSymbolAddress((void**)&pV, g_V);
    cudaGetSymbolAddress((void**)&pC, g_ctx);

    cudaFuncSetAttribute(attn2_kernel,
                         cudaFuncAttributeMaxDynamicSharedMemorySize,
                         ATTN_SMEM_BYTES);

    dim3 pg(DM / 128, MTOT / 128);   // (8, 32)
    proj2_kernel<1><<<pg, 256>>>(query, Wq, bq, pQ);
    proj2_kernel<1><<<pg, 256>>>(key,   Wk, bk, pK);
    proj2_kernel<1><<<pg, 256>>>(value, Wv, bv, pV);

    dim3 ag(BZ * NH, SQ / AM);       // (32, 16)
    attn2_kernel<<<ag, 256, ATTN_SMEM_BYTES>>>(pQ, pK, pV, pC);

    proj2_kernel<0><<<pg, 256>>>(pC, Wo, bo, out);
}

// round 7
// speedup vs baseline: 1.6177x; 1.2819x over previous
#include <cuda_runtime.h>
#include <cstdint>
#include <math.h>

// Problem constants (fixed by the reference).
#define BZ   2
#define SQ   2048
#define DM   1024
#define NH   16
#define HD   64
#define MTOT (BZ * SQ)   // 4096

// ---------------------------------------------------------------------------
// mma.sync / ldmatrix helpers (family-portable PTX: compiles for compute_103)
// ---------------------------------------------------------------------------
__device__ __forceinline__ uint32_t smem_u32(const void* p) {
    uint32_t a;
    asm("{ .reg .u64 t; cvta.to.shared.u64 t, %1; cvt.u32.u64 %0, t; }"
        : "=r"(a) : "l"(p));
    return a;
}

__device__ __forceinline__ void ldm4(uint32_t* r, uint32_t addr) {
    asm volatile("ldmatrix.sync.aligned.m8n8.x4.shared.b16 {%0,%1,%2,%3}, [%4];"
                 : "=r"(r[0]), "=r"(r[1]), "=r"(r[2]), "=r"(r[3]) : "r"(addr));
}

// d += a(tf32) * b(tf32), m16n8k8, fp32 accumulate
__device__ __forceinline__ void mma_tf32(float* d, const uint32_t* a,
                                         uint32_t b0, uint32_t b1) {
    asm volatile(
        "mma.sync.aligned.m16n8k8.row.col.f32.tf32.tf32.f32 "
        "{%0,%1,%2,%3}, {%4,%5,%6,%7}, {%8,%9}, {%0,%1,%2,%3};"
        : "+f"(d[0]), "+f"(d[1]), "+f"(d[2]), "+f"(d[3])
        : "r"(a[0]), "r"(a[1]), "r"(a[2]), "r"(a[3]), "r"(b0), "r"(b1));
}

// split fp32 -> tf32 hi + fp32 lo (lo truncates harmlessly inside the MMA)
__device__ __forceinline__ void split4(const uint32_t* x, uint32_t* hi, uint32_t* lo) {
#pragma unroll
    for (int i = 0; i < 4; i++) {
        uint32_t h;
        asm("cvt.rna.tf32.f32 %0, %1;" : "=r"(h) : "r"(x[i]));
        hi[i] = h;
        lo[i] = __float_as_uint(__uint_as_float(x[i]) - __uint_as_float(h));
    }
}

// ---------------------------------------------------------------------------
// Scratch (device globals: no allocation allowed in kernel_launch)
// ---------------------------------------------------------------------------
__device__ float g_Q[BZ * NH * SQ * HD];    // [B,H,S,Hd]
__device__ float g_K[BZ * NH * SQ * HD];
__device__ float g_V[BZ * NH * SQ * HD];
__device__ float g_ctx[BZ * SQ * DM];       // [B,S,D]

// ---------------------------------------------------------------------------
// proj4: tf32x3 mma.sync GEMM.  Y[m,n] = sum_k X[m,k]W[n,k] + bias[n]
// CTA tile 128x128, BK=32, 256 threads (8 warps in 2Mx4N grid, warp tile 64x32).
// smem rows stride 36 floats (144B, ≡4 mod 32 banks -> ldmatrix conflict-free).
// ---------------------------------------------------------------------------
#define PSTRIDE 36
#define PBK 32

template <int HEAD_LAYOUT>
__global__ __launch_bounds__(256)
void proj4_kernel(const float* __restrict__ X, const float* __restrict__ W,
                  const float* __restrict__ bias, float* __restrict__ Y)
{
    __shared__ float As[128 * PSTRIDE];
    __shared__ float Bs[128 * PSTRIDE];

    const int tid = threadIdx.x, lane = tid & 31, wid = tid >> 5;
    const int wm = wid & 1, wn = wid >> 1;          // warp: rows 64*wm, cols 32*wn
    const int mb_blk = blockIdx.y * 128, nb_blk = blockIdx.x * 128;

    const float* Xp = X + (size_t)mb_blk * DM;
    const float* Wp = W + (size_t)nb_blk * DM;

    int lrow[4], lcw[4];
#pragma unroll
    for (int j = 0; j < 4; j++) { int id = tid + 256 * j; lrow[j] = id >> 3; lcw[j] = (id & 7) * 4; }

    float4 xa[4], wb[4];
#pragma unroll
    for (int j = 0; j < 4; j++) {
        xa[j] = *(const float4*)(Xp + (size_t)lrow[j] * DM + lcw[j]);
        wb[j] = *(const float4*)(Wp + (size_t)lrow[j] * DM + lcw[j]);
    }

    float acc[4][4][4];
#pragma unroll
    for (int i = 0; i < 4; i++)
#pragma unroll
        for (int j = 0; j < 4; j++)
#pragma unroll
            for (int r = 0; r < 4; r++) acc[i][j][r] = 0.f;

    // per-lane ldmatrix byte offsets
    const uint32_t a_base = smem_u32(As), b_base = smem_u32(Bs);
    const uint32_t a_off = a_base + (((64 * wm + (lane & 15)) * PSTRIDE) + ((lane >> 4) << 2)) * 4;
    const uint32_t b_off = b_base + (((32 * wn + (lane & 7) + ((lane >> 4) << 3)) * PSTRIDE)
                                     + (((lane >> 3) & 1) << 2)) * 4;

    for (int kc = 0; kc < DM / PBK; kc++) {
        __syncthreads();
#pragma unroll
        for (int j = 0; j < 4; j++) {
            *(float4*)(As + lrow[j] * PSTRIDE + lcw[j]) = xa[j];
            *(float4*)(Bs + lrow[j] * PSTRIDE + lcw[j]) = wb[j];
        }
        __syncthreads();
        if (kc + 1 < DM / PBK) {
#pragma unroll
            for (int j = 0; j < 4; j++) {
                xa[j] = *(const float4*)(Xp + (size_t)lrow[j] * DM + (kc + 1) * PBK + lcw[j]);
                wb[j] = *(const float4*)(Wp + (size_t)lrow[j] * DM + (kc + 1) * PBK + lcw[j]);
            }
        }
#pragma unroll
        for (int s = 0; s < 4; s++) {
            const uint32_t koff = 32 * s;   // 8 floats = 32 bytes
#pragma unroll
            for (int mt = 0; mt < 4; mt++) {
                uint32_t a[4], ah[4], al[4];
                ldm4(a, a_off + (16 * mt * PSTRIDE) * 4 + koff);
                split4(a, ah, al);
#pragma unroll
                for (int pr = 0; pr < 2; pr++) {
                    uint32_t b[4], bh[4], bl[4];
                    ldm4(b, b_off + (16 * pr * PSTRIDE) * 4 + koff);
                    split4(b, bh, bl);
                    mma_tf32(acc[mt][2 * pr],     ah, bh[0], bh[1]);
                    mma_tf32(acc[mt][2 * pr],     ah, bl[0], bl[1]);
                    mma_tf32(acc[mt][2 * pr],     al, bh[0], bh[1]);
                    mma_tf32(acc[mt][2 * pr + 1], ah, bh[2], bh[3]);
                    mma_tf32(acc[mt][2 * pr + 1], ah, bl[2], bl[3]);
                    mma_tf32(acc[mt][2 * pr + 1], al, bh[2], bh[3]);
                }
            }
        }
    }

    // epilogue: D-frag rows g,g+8; cols 2t,2t+1
    const int g = lane >> 2, t = lane & 3;
#pragma unroll
    for (int mt = 0; mt < 4; mt++) {
#pragma unroll
        for (int nt = 0; nt < 4; nt++) {
            int n = nb_blk + 32 * wn + 8 * nt + 2 * t;
            float2 bv = *(const float2*)(bias + n);
            float v00 = acc[mt][nt][0] + bv.x, v01 = acc[mt][nt][1] + bv.y;
            float v10 = acc[mt][nt][2] + bv.x, v11 = acc[mt][nt][3] + bv.y;
            int m = mb_blk + 64 * wm + 16 * mt + g;
            if (HEAD_LAYOUT) {
                int b = m >> 11, s = m & (SQ - 1);
                int h = n >> 6, hd = n & 63;
                float* p0 = g_Q; (void)p0;
                size_t base = (((size_t)b * NH + h) * SQ + s) * HD + hd;
                *(float2*)(Y + base) = make_float2(v00, v01);
                *(float2*)(Y + base + 8 * HD) = make_float2(v10, v11);
            } else {
                *(float2*)(Y + (size_t)m * DM + n) = make_float2(v00, v01);
                *(float2*)(Y + (size_t)(m + 8) * DM + n) = make_float2(v10, v11);
            }
        }
    }
}

// ---------------------------------------------------------------------------
// attn3: flash attention, tf32x3 mma.sync for QK^T and PV.
// CTA: 128 q-rows, key tiles of 64. 8 warps; warp w owns rows 16w..16w+15,
// so softmax rows never cross warps (quad shuffles only).
// smem rows stride 68 floats (conflict-free ldmatrix phases).
// ---------------------------------------------------------------------------
#define ASTR 68
#define AQ_OFF 0
#define AK_OFF (128 * ASTR)
#define AV_OFF (AK_OFF + 64 * ASTR)
#define AP_OFF (AV_OFF + 64 * ASTR)
#define ATTN_SMEM_FLOATS (AP_OFF + 128 * ASTR)
#define ATTN_SMEM_BYTES  (ATTN_SMEM_FLOATS * 4)   // 104448

__global__ __launch_bounds__(256)
void attn3_kernel(const float* __restrict__ Q, const float* __restrict__ K,
                  const float* __restrict__ V, float* __restrict__ ctx)
{
    extern __shared__ float sm[];
    float* Qsm = sm + AQ_OFF;      // [m=128][hd] stride 68
    float* Ksm = sm + AK_OFF;      // [s=64][hd]  stride 68
    float* Vsm = sm + AV_OFF;      // [hd=64][s]  stride 68  (transposed)
    float* Psm = sm + AP_OFF;      // [m=128][s]  stride 68

    const int bh = blockIdx.x, m0 = blockIdx.y * 128;
    const int tid = threadIdx.x, lane = tid & 31, wid = tid >> 5;
    const int g = lane >> 2, t = lane & 3;

    const float* Qb = Q + (size_t)bh * SQ * HD;
    const float* Kb = K + (size_t)bh * SQ * HD;
    const float* Vb = V + (size_t)bh * SQ * HD;

    // load Q tile once, pre-scaled by 1/sqrt(64)
#pragma unroll
    for (int j = 0; j < 8; j++) {
        int id = tid + 256 * j;
        int row = id >> 4, cw = (id & 15) * 4;
        float4 q = *(const float4*)(Qb + (size_t)(m0 + row) * HD + cw);
        q.x *= 0.125f; q.y *= 0.125f; q.z *= 0.125f; q.w *= 0.125f;
        *(float4*)(Qsm + row * ASTR + cw) = q;
    }

    // per-lane ldmatrix byte offsets
    const uint32_t arow = 16 * wid + (lane & 15);
    const uint32_t acolB = ((lane >> 4) << 2) * 4;
    const uint32_t qa_off = smem_u32(Qsm) + (arow * ASTR) * 4 + acolB;
    const uint32_t pa_off = smem_u32(Psm) + (arow * ASTR) * 4 + acolB;
    const uint32_t brow = (lane & 7) + ((lane >> 4) << 3);
    const uint32_t bcolB = (((lane >> 3) & 1) << 2) * 4;
    const uint32_t kb_off = smem_u32(Ksm) + (brow * ASTR) * 4 + bcolB;
    const uint32_t vb_off = smem_u32(Vsm) + (brow * ASTR) * 4 + bcolB;

    float oacc[8][4];
#pragma unroll
    for (int i = 0; i < 8; i++)
#pragma unroll
        for (int r = 0; r < 4; r++) oacc[i][r] = 0.f;
    float mi[2] = {-1e30f, -1e30f}, li[2] = {0.f, 0.f};

    for (int kt0 = 0; kt0 < SQ; kt0 += 64) {
        __syncthreads();
        // K tile: direct copy (coalesced)
#pragma unroll
        for (int j = 0; j < 4; j++) {
            int id = tid + 256 * j;
            int row = id >> 4, cw = (id & 15) * 4;
            *(float4*)(Ksm + row * ASTR + cw) =
                *(const float4*)(Kb + (size_t)(kt0 + row) * HD + cw);
        }
        // V tile: transpose into [hd][s] (conflict-free scalar stores)
#pragma unroll
        for (int j = 0; j < 4; j++) {
            int id = tid + 256 * j;
            int row = id & 63, cw = (id >> 6) * 4;
            float4 v = *(const float4*)(Vb + (size_t)(kt0 + row) * HD + cw);
            Vsm[(cw + 0) * ASTR + row] = v.x;
            Vsm[(cw + 1) * ASTR + row] = v.y;
            Vsm[(cw + 2) * ASTR + row] = v.z;
            Vsm[(cw + 3) * ASTR + row] = v.w;
        }
        __syncthreads();

        // ---- QK^T: S[16 x 64] per warp ----
        float sacc[8][4];
#pragma unroll
        for (int i = 0; i < 8; i++)
#pragma unroll
            for (int r = 0; r < 4; r++) sacc[i][r] = 0.f;

#pragma unroll
        for (int s = 0; s < 8; s++) {
            const uint32_t koff = 32 * s;
            uint32_t a[4], ah[4], al[4];
            ldm4(a, qa_off + koff);
            split4(a, ah, al);
#pragma unroll
            for (int pr = 0; pr < 4; pr++) {
                uint32_t b[4], bh[4], bl[4];
                ldm4(b, kb_off + (16 * pr * ASTR) * 4 + koff);
                split4(b, bh, bl);
                mma_tf32(sacc[2 * pr],     ah, bh[0], bh[1]);
                mma_tf32(sacc[2 * pr],     ah, bl[0], bl[1]);
                mma_tf32(sacc[2 * pr],     al, bh[0], bh[1]);
                mma_tf32(sacc[2 * pr + 1], ah, bh[2], bh[3]);
                mma_tf32(sacc[2 * pr + 1], ah, bl[2], bl[3]);
                mma_tf32(sacc[2 * pr + 1], al, bh[2], bh[3]);
            }
        }

        // ---- online softmax (rows g, g+8; quad-wide reductions) ----
        float mx0 = -1e30f, mx1 = -1e30f;
#pragma unroll
        for (int ntl = 0; ntl < 8; ntl++) {
            mx0 = fmaxf(mx0, fmaxf(sacc[ntl][0], sacc[ntl][1]));
            mx1 = fmaxf(mx1, fmaxf(sacc[ntl][2], sacc[ntl][3]));
        }
#pragma unroll
        for (int o = 1; o < 4; o <<= 1) {
            mx0 = fmaxf(mx0, __shfl_xor_sync(0xffffffffu, mx0, o, 4));
            mx1 = fmaxf(mx1, __shfl_xor_sync(0xffffffffu, mx1, o, 4));
        }
        float mn0 = fmaxf(mi[0], mx0), mn1 = fmaxf(mi[1], mx1);
        float corr0 = __expf(mi[0] - mn0), corr1 = __expf(mi[1] - mn1);
        mi[0] = mn0; mi[1] = mn1;
        float rs0 = 0.f, rs1 = 0.f;
#pragma unroll
        for (int ntl = 0; ntl < 8; ntl++) {
            sacc[ntl][0] = __expf(sacc[ntl][0] - mn0); rs0 += sacc[ntl][0];
            sacc[ntl][1] = __expf(sacc[ntl][1] - mn0); rs0 += sacc[ntl][1];
            sacc[ntl][2] = __expf(sacc[ntl][2] - mn1); rs1 += sacc[ntl][2];
            sacc[ntl][3] = __expf(sacc[ntl][3] - mn1); rs1 += sacc[ntl][3];
        }
#pragma unroll
        for (int o = 1; o < 4; o <<= 1) {
            rs0 += __shfl_xor_sync(0xffffffffu, rs0, o, 4);
            rs1 += __shfl_xor_sync(0xffffffffu, rs1, o, 4);
        }
        li[0] = li[0] * corr0 + rs0;
        li[1] = li[1] * corr1 + rs1;
#pragma unroll
        for (int ntl = 0; ntl < 8; ntl++) {
            oacc[ntl][0] *= corr0; oacc[ntl][1] *= corr0;
            oacc[ntl][2] *= corr1; oacc[ntl][3] *= corr1;
        }

        // ---- store P (own warp's rows only) ----
#pragma unroll
        for (int ntl = 0; ntl < 8; ntl++) {
            int c = 8 * ntl + 2 * t;
            *(float2*)(Psm + (16 * wid + g) * ASTR + c) =
                make_float2(sacc[ntl][0], sacc[ntl][1]);
            *(float2*)(Psm + (16 * wid + g + 8) * ASTR + c) =
                make_float2(sacc[ntl][2], sacc[ntl][3]);
        }
        __syncwarp();

        // ---- PV: O[16 x 64] += P[16 x 64] * V[64 x 64] ----
#pragma unroll
        for (int s = 0; s < 8; s++) {
            const uint32_t koff = 32 * s;
            uint32_t p[4], ph[4], pl[4];
            ldm4(p, pa_off + koff);
            split4(p, ph, pl);
#pragma unroll
            for (int pr = 0; pr < 4; pr++) {
                uint32_t v[4], vh[4], vl[4];
                ldm4(v, vb_off + (16 * pr * ASTR) * 4 + koff);
                split4(v, vh, vl);
                mma_tf32(oacc[2 * pr],     ph, vh[0], vh[1]);
                mma_tf32(oacc[2 * pr],     ph, vl[0], vl[1]);
                mma_tf32(oacc[2 * pr],     pl, vh[0], vh[1]);
                mma_tf32(oacc[2 * pr + 1], ph, vh[2], vh[3]);
                mma_tf32(oacc[2 * pr + 1], ph, vl[2], vl[3]);
                mma_tf32(oacc[2 * pr + 1], pl, vh[2], vh[3]);
            }
        }
    }

    // ---- normalize + write ctx [B,S,D] ----
    const int b = bh >> 4, h = bh & 15;
    const float inv0 = 1.f / li[0], inv1 = 1.f / li[1];
    const int row0 = m0 + 16 * wid + g;
#pragma unroll
    for (int ntl = 0; ntl < 8; ntl++) {
        int col = h * HD + 8 * ntl + 2 * t;
        *(float2*)(ctx + ((size_t)b * SQ + row0) * DM + col) =
            make_float2(oacc[ntl][0] * inv0, oacc[ntl][1] * inv0);
        *(float2*)(ctx + ((size_t)b * SQ + row0 + 8) * DM + col) =
            make_float2(oacc[ntl][2] * inv1, oacc[ntl][3] * inv1);
    }
}

// ---------------------------------------------------------------------------
// Launch
// ---------------------------------------------------------------------------
extern "C" void kernel_launch(void* const* d_in, const int* in_sizes, int n_in,
                              void* d_out, int out_size)
{
    const float* query = (const float*)d_in[0];
    const float* key   = (const float*)d_in[1];
    const float* value = (const float*)d_in[2];
    const float* Wq = (const float*)d_in[3];
    const float* bq = (const float*)d_in[4];
    const float* Wk = (const float*)d_in[5];
    const float* bk = (const float*)d_in[6];
    const float* Wv = (const float*)d_in[7];
    const float* bv = (const float*)d_in[8];
    const float* Wo = (const float*)d_in[9];
    const float* bo = (const float*)d_in[10];
    float* out = (float*)d_out;

    float *pQ, *pK, *pV, *pC;
    cudaGetSymbolAddress((void**)&pQ, g_Q);
    cudaGetSymbolAddress((void**)&pK, g_K);
    cudaGetSymbolAddress((void**)&pV, g_V);
    cudaGetSymbolAddress((void**)&pC, g_ctx);

    cudaFuncSetAttribute(attn3_kernel,
                         cudaFuncAttributeMaxDynamicSharedMemorySize,
                         ATTN_SMEM_BYTES);

    dim3 pg(DM / 128, MTOT / 128);   // (8, 32)
    proj4_kernel<1><<<pg, 256>>>(query, Wq, bq, pQ);
    proj4_kernel<1><<<pg, 256>>>(key,   Wk, bk, pK);
    proj4_kernel<1><<<pg, 256>>>(value, Wv, bv, pV);

    dim3 ag(BZ * NH, SQ / 128);      // (32, 16)
    attn3_kernel<<<ag, 256, ATTN_SMEM_BYTES>>>(pQ, pK, pV, pC);

    proj4_kernel<0><<<pg, 256>>>(pC, Wo, bo, out);
}

// round 9
// speedup vs baseline: 1.6512x; 1.0208x over previous
#include <cuda_runtime.h>
#include <cstdint>
#include <math.h>

// Problem constants (fixed by the reference).
#define BZ   2
#define SQ   2048
#define DM   1024
#define NH   16
#define HD   64
#define MTOT (BZ * SQ)   // 4096

// ---------------------------------------------------------------------------
// mma.sync / ldmatrix helpers (family-portable PTX: compiles for compute_103)
// ---------------------------------------------------------------------------
__device__ __forceinline__ uint32_t smem_u32(const void* p) {
    uint32_t a;
    asm("{ .reg .u64 t; cvta.to.shared.u64 t, %1; cvt.u32.u64 %0, t; }"
        : "=r"(a) : "l"(p));
    return a;
}

__device__ __forceinline__ void ldm4(uint32_t* r, uint32_t addr) {
    asm volatile("ldmatrix.sync.aligned.m8n8.x4.shared.b16 {%0,%1,%2,%3}, [%4];"
                 : "=r"(r[0]), "=r"(r[1]), "=r"(r[2]), "=r"(r[3]) : "r"(addr));
}

// d += a(tf32) * b(tf32), m16n8k8, fp32 accumulate
__device__ __forceinline__ void mma_tf32(float* d, const uint32_t* a,
                                         uint32_t b0, uint32_t b1) {
    asm volatile(
        "mma.sync.aligned.m16n8k8.row.col.f32.tf32.tf32.f32 "
        "{%0,%1,%2,%3}, {%4,%5,%6,%7}, {%8,%9}, {%0,%1,%2,%3};"
        : "+f"(d[0]), "+f"(d[1]), "+f"(d[2]), "+f"(d[3])
        : "r"(a[0]), "r"(a[1]), "r"(a[2]), "r"(a[3]), "r"(b0), "r"(b1));
}

// split fp32 -> tf32 hi + fp32 lo (lo truncates harmlessly inside the MMA)
__device__ __forceinline__ void split4(const uint32_t* x, uint32_t* hi, uint32_t* lo) {
#pragma unroll
    for (int i = 0; i < 4; i++) {
        uint32_t h;
        asm("cvt.rna.tf32.f32 %0, %1;" : "=r"(h) : "r"(x[i]));
        hi[i] = h;
        lo[i] = __float_as_uint(__uint_as_float(x[i]) - __uint_as_float(h));
    }
}

// ---------------------------------------------------------------------------
// Scratch (device globals: no allocation allowed in kernel_launch)
// ---------------------------------------------------------------------------
__device__ float g_Q[BZ * NH * SQ * HD];    // [B,H,S,Hd]
__device__ float g_K[BZ * NH * SQ * HD];
__device__ float g_V[BZ * NH * SQ * HD];
__device__ float g_ctx[BZ * SQ * DM];       // [B,S,D]

// ---------------------------------------------------------------------------
// proj4: tf32x3 mma.sync GEMM.  Y[m,n] = sum_k X[m,k]W[n,k] + bias[n]
// CTA tile 128x128, BK=32, 256 threads (8 warps in 2Mx4N grid, warp tile 64x32).
// __launch_bounds__(256,2): <=128 regs -> 2 CTAs/SM -> grid runs in ONE wave.
// ---------------------------------------------------------------------------
#define PSTRIDE 36
#define PBK 32

template <int HEAD_LAYOUT>
__global__ __launch_bounds__(256, 2)
void proj4_kernel(const float* __restrict__ X, const float* __restrict__ W,
                  const float* __restrict__ bias, float* __restrict__ Y)
{
    __shared__ float As[128 * PSTRIDE];
    __shared__ float Bs[128 * PSTRIDE];

    const int tid = threadIdx.x, lane = tid & 31, wid = tid >> 5;
    const int wm = wid & 1, wn = wid >> 1;          // warp: rows 64*wm, cols 32*wn
    const int mb_blk = blockIdx.y * 128, nb_blk = blockIdx.x * 128;

    const float* Xp = X + (size_t)mb_blk * DM;
    const float* Wp = W + (size_t)nb_blk * DM;

    int lrow[4], lcw[4];
#pragma unroll
    for (int j = 0; j < 4; j++) { int id = tid + 256 * j; lrow[j] = id >> 3; lcw[j] = (id & 7) * 4; }

    float4 xa[4], wb[4];
#pragma unroll
    for (int j = 0; j < 4; j++) {
        xa[j] = *(const float4*)(Xp + (size_t)lrow[j] * DM + lcw[j]);
        wb[j] = *(const float4*)(Wp + (size_t)lrow[j] * DM + lcw[j]);
    }

    float acc[4][4][4];
#pragma unroll
    for (int i = 0; i < 4; i++)
#pragma unroll
        for (int j = 0; j < 4; j++)
#pragma unroll
            for (int r = 0; r < 4; r++) acc[i][j][r] = 0.f;

    // per-lane ldmatrix byte offsets
    const uint32_t a_base = smem_u32(As), b_base = smem_u32(Bs);
    const uint32_t a_off = a_base + (((64 * wm + (lane & 15)) * PSTRIDE) + ((lane >> 4) << 2)) * 4;
    const uint32_t b_off = b_base + (((32 * wn + (lane & 7) + ((lane >> 4) << 3)) * PSTRIDE)
                                     + (((lane >> 3) & 1) << 2)) * 4;

    for (int kc = 0; kc < DM / PBK; kc++) {
        __syncthreads();
#pragma unroll
        for (int j = 0; j < 4; j++) {
            *(float4*)(As + lrow[j] * PSTRIDE + lcw[j]) = xa[j];
            *(float4*)(Bs + lrow[j] * PSTRIDE + lcw[j]) = wb[j];
        }
        __syncthreads();
        if (kc + 1 < DM / PBK) {
#pragma unroll
            for (int j = 0; j < 4; j++) {
                xa[j] = *(const float4*)(Xp + (size_t)lrow[j] * DM + (kc + 1) * PBK + lcw[j]);
                wb[j] = *(const float4*)(Wp + (size_t)lrow[j] * DM + (kc + 1) * PBK + lcw[j]);
            }
        }
#pragma unroll
        for (int s = 0; s < 4; s++) {
            const uint32_t koff = 32 * s;   // 8 floats = 32 bytes
#pragma unroll
            for (int mt = 0; mt < 4; mt++) {
                uint32_t a[4], ah[4], al[4];
                ldm4(a, a_off + (16 * mt * PSTRIDE) * 4 + koff);
                split4(a, ah, al);
#pragma unroll
                for (int pr = 0; pr < 2; pr++) {
                    uint32_t b[4], bh[4], bl[4];
                    ldm4(b, b_off + (16 * pr * PSTRIDE) * 4 + koff);
                    split4(b, bh, bl);
                    mma_tf32(acc[mt][2 * pr],     ah, bh[0], bh[1]);
                    mma_tf32(acc[mt][2 * pr],     ah, bl[0], bl[1]);
                    mma_tf32(acc[mt][2 * pr],     al, bh[0], bh[1]);
                    mma_tf32(acc[mt][2 * pr + 1], ah, bh[2], bh[3]);
                    mma_tf32(acc[mt][2 * pr + 1], ah, bl[2], bl[3]);
                    mma_tf32(acc[mt][2 * pr + 1], al, bh[2], bh[3]);
                }
            }
        }
    }

    // epilogue: D-frag rows g,g+8; cols 2t,2t+1
    const int g = lane >> 2, t = lane & 3;
#pragma unroll
    for (int mt = 0; mt < 4; mt++) {
#pragma unroll
        for (int nt = 0; nt < 4; nt++) {
            int n = nb_blk + 32 * wn + 8 * nt + 2 * t;
            float2 bv = *(const float2*)(bias + n);
            float v00 = acc[mt][nt][0] + bv.x, v01 = acc[mt][nt][1] + bv.y;
            float v10 = acc[mt][nt][2] + bv.x, v11 = acc[mt][nt][3] + bv.y;
            int m = mb_blk + 64 * wm + 16 * mt + g;
            if (HEAD_LAYOUT) {
                int b = m >> 11, s = m & (SQ - 1);
                int h = n >> 6, hd = n & 63;
                size_t base = (((size_t)b * NH + h) * SQ + s) * HD + hd;
                *(float2*)(Y + base) = make_float2(v00, v01);
                *(float2*)(Y + base + 8 * HD) = make_float2(v10, v11);
            } else {
                *(float2*)(Y + (size_t)m * DM + n) = make_float2(v00, v01);
                *(float2*)(Y + (size_t)(m + 8) * DM + n) = make_float2(v10, v11);
            }
        }
    }
}

// ---------------------------------------------------------------------------
// attn3: flash attention, tf32x3 mma.sync for QK^T and PV.
// CTA: 128 q-rows, key tiles of 64. 8 warps; warp w owns rows 16w..16w+15.
// __launch_bounds__(256,2): <=128 regs so smem(102KB)x2 + regs fit 2 CTAs/SM
// -> 16 warps/SM (occupancy was the R6 binding constraint, regfile-capped).
// ---------------------------------------------------------------------------
#define ASTR 68
#define AQ_OFF 0
#define AK_OFF (128 * ASTR)
#define AV_OFF (AK_OFF + 64 * ASTR)
#define AP_OFF (AV_OFF + 64 * ASTR)
#define ATTN_SMEM_FLOATS (AP_OFF + 128 * ASTR)
#define ATTN_SMEM_BYTES  (ATTN_SMEM_FLOATS * 4)   // 104448

__global__ __launch_bounds__(256, 2)
void attn3_kernel(const float* __restrict__ Q, const float* __restrict__ K,
                  const float* __restrict__ V, float* __restrict__ ctx)
{
    extern __shared__ float sm[];
    float* Qsm = sm + AQ_OFF;      // [m=128][hd] stride 68
    float* Ksm = sm + AK_OFF;      // [s=64][hd]  stride 68
    float* Vsm = sm + AV_OFF;      // [hd=64][s]  stride 68  (transposed)
    float* Psm = sm + AP_OFF;      // [m=128][s]  stride 68

    const int bh = blockIdx.x, m0 = blockIdx.y * 128;
    const int tid = threadIdx.x, lane = tid & 31, wid = tid >> 5;
    const int g = lane >> 2, t = lane & 3;

    const float* Qb = Q + (size_t)bh * SQ * HD;
    const float* Kb = K + (size_t)bh * SQ * HD;
    const float* Vb = V + (size_t)bh * SQ * HD;

    // load Q tile once, pre-scaled by 1/sqrt(64)
#pragma unroll
    for (int j = 0; j < 8; j++) {
        int id = tid + 256 * j;
        int row = id >> 4, cw = (id & 15) * 4;
        float4 q = *(const float4*)(Qb + (size_t)(m0 + row) * HD + cw);
        q.x *= 0.125f; q.y *= 0.125f; q.z *= 0.125f; q.w *= 0.125f;
        *(float4*)(Qsm + row * ASTR + cw) = q;
    }

    // per-lane ldmatrix byte offsets
    const uint32_t arow = 16 * wid + (lane & 15);
    const uint32_t acolB = ((lane >> 4) << 2) * 4;
    const uint32_t qa_off = smem_u32(Qsm) + (arow * ASTR) * 4 + acolB;
    const uint32_t pa_off = smem_u32(Psm) + (arow * ASTR) * 4 + acolB;
    const uint32_t brow = (lane & 7) + ((lane >> 4) << 3);
    const uint32_t bcolB = (((lane >> 3) & 1) << 2) * 4;
    const uint32_t kb_off = smem_u32(Ksm) + (brow * ASTR) * 4 + bcolB;
    const uint32_t vb_off = smem_u32(Vsm) + (brow * ASTR) * 4 + bcolB;

    float oacc[8][4];
#pragma unroll
    for (int i = 0; i < 8; i++)
#pragma unroll
        for (int r = 0; r < 4; r++) oacc[i][r] = 0.f;
    float mi[2] = {-1e30f, -1e30f}, li[2] = {0.f, 0.f};

    for (int kt0 = 0; kt0 < SQ; kt0 += 64) {
        __syncthreads();
        // K tile: direct copy (coalesced)
#pragma unroll
        for (int j = 0; j < 4; j++) {
            int id = tid + 256 * j;
            int row = id >> 4, cw = (id & 15) * 4;
            *(float4*)(Ksm + row * ASTR + cw) =
                *(const float4*)(Kb + (size_t)(kt0 + row) * HD + cw);
        }
        // V tile: transpose into [hd][s] (conflict-free scalar stores)
#pragma unroll
        for (int j = 0; j < 4; j++) {
            int id = tid + 256 * j;
            int row = id & 63, cw = (id >> 6) * 4;
            float4 v = *(const float4*)(Vb + (size_t)(kt0 + row) * HD + cw);
            Vsm[(cw + 0) * ASTR + row] = v.x;
            Vsm[(cw + 1) * ASTR + row] = v.y;
            Vsm[(cw + 2) * ASTR + row] = v.z;
            Vsm[(cw + 3) * ASTR + row] = v.w;
        }
        __syncthreads();

        // ---- QK^T: S[16 x 64] per warp ----
        float sacc[8][4];
#pragma unroll
        for (int i = 0; i < 8; i++)
#pragma unroll
            for (int r = 0; r < 4; r++) sacc[i][r] = 0.f;

#pragma unroll
        for (int s = 0; s < 8; s++) {
            const uint32_t koff = 32 * s;
            uint32_t a[4], ah[4], al[4];
            ldm4(a, qa_off + koff);
            split4(a, ah, al);
#pragma unroll
            for (int pr = 0; pr < 4; pr++) {
                uint32_t b[4], bh[4], bl[4];
                ldm4(b, kb_off + (16 * pr * ASTR) * 4 + koff);
                split4(b, bh, bl);
                mma_tf32(sacc[2 * pr],     ah, bh[0], bh[1]);
                mma_tf32(sacc[2 * pr],     ah, bl[0], bl[1]);
                mma_tf32(sacc[2 * pr],     al, bh[0], bh[1]);
                mma_tf32(sacc[2 * pr + 1], ah, bh[2], bh[3]);
                mma_tf32(sacc[2 * pr + 1], ah, bl[2], bl[3]);
                mma_tf32(sacc[2 * pr + 1], al, bh[2], bh[3]);
            }
        }

        // ---- online softmax (rows g, g+8; quad-wide reductions) ----
        float mx0 = -1e30f, mx1 = -1e30f;
#pragma unroll
        for (int ntl = 0; ntl < 8; ntl++) {
            mx0 = fmaxf(mx0, fmaxf(sacc[ntl][0], sacc[ntl][1]));
            mx1 = fmaxf(mx1, fmaxf(sacc[ntl][2], sacc[ntl][3]));
        }
#pragma unroll
        for (int o = 1; o < 4; o <<= 1) {
            mx0 = fmaxf(mx0, __shfl_xor_sync(0xffffffffu, mx0, o, 4));
            mx1 = fmaxf(mx1, __shfl_xor_sync(0xffffffffu, mx1, o, 4));
        }
        float mn0 = fmaxf(mi[0], mx0), mn1 = fmaxf(mi[1], mx1);
        float corr0 = __expf(mi[0] - mn0), corr1 = __expf(mi[1] - mn1);
        mi[0] = mn0; mi[1] = mn1;
        float rs0 = 0.f, rs1 = 0.f;
#pragma unroll
        for (int ntl = 0; ntl < 8; ntl++) {
            sacc[ntl][0] = __expf(sacc[ntl][0] - mn0); rs0 += sacc[ntl][0];
            sacc[ntl][1] = __expf(sacc[ntl][1] - mn0); rs0 += sacc[ntl][1];
            sacc[ntl][2] = __expf(sacc[ntl][2] - mn1); rs1 += sacc[ntl][2];
            sacc[ntl][3] = __expf(sacc[ntl][3] - mn1); rs1 += sacc[ntl][3];
        }
#pragma unroll
        for (int o = 1; o < 4; o <<= 1) {
            rs0 += __shfl_xor_sync(0xffffffffu, rs0, o, 4);
            rs1 += __shfl_xor_sync(0xffffffffu, rs1, o, 4);
        }
        li[0] = li[0] * corr0 + rs0;
        li[1] = li[1] * corr1 + rs1;
#pragma unroll
        for (int ntl = 0; ntl < 8; ntl++) {
            oacc[ntl][0] *= corr0; oacc[ntl][1] *= corr0;
            oacc[ntl][2] *= corr1; oacc[ntl][3] *= corr1;
        }

        // ---- store P (own warp's rows only) ----
#pragma unroll
        for (int ntl = 0; ntl < 8; ntl++) {
            int c = 8 * ntl + 2 * t;
            *(float2*)(Psm + (16 * wid + g) * ASTR + c) =
                make_float2(sacc[ntl][0], sacc[ntl][1]);
            *(float2*)(Psm + (16 * wid + g + 8) * ASTR + c) =
                make_float2(sacc[ntl][2], sacc[ntl][3]);
        }
        __syncwarp();

        // ---- PV: O[16 x 64] += P[16 x 64] * V[64 x 64] ----
#pragma unroll
        for (int s = 0; s < 8; s++) {
            const uint32_t koff = 32 * s;
            uint32_t p[4], ph[4], pl[4];
            ldm4(p, pa_off + koff);
            split4(p, ph, pl);
#pragma unroll
            for (int pr = 0; pr < 4; pr++) {
                uint32_t v[4], vh[4], vl[4];
                ldm4(v, vb_off + (16 * pr * ASTR) * 4 + koff);
                split4(v, vh, vl);
                mma_tf32(oacc[2 * pr],     ph, vh[0], vh[1]);
                mma_tf32(oacc[2 * pr],     ph, vl[0], vl[1]);
                mma_tf32(oacc[2 * pr],     pl, vh[0], vh[1]);
                mma_tf32(oacc[2 * pr + 1], ph, vh[2], vh[3]);
                mma_tf32(oacc[2 * pr + 1], ph, vl[2], vl[3]);
                mma_tf32(oacc[2 * pr + 1], pl, vh[2], vh[3]);
            }
        }
    }

    // ---- normalize + write ctx [B,S,D] ----
    const int b = bh >> 4, h = bh & 15;
    const float inv0 = 1.f / li[0], inv1 = 1.f / li[1];
    const int row0 = m0 + 16 * wid + g;
#pragma unroll
    for (int ntl = 0; ntl < 8; ntl++) {
        int col = h * HD + 8 * ntl + 2 * t;
        *(float2*)(ctx + ((size_t)b * SQ + row0) * DM + col) =
            make_float2(oacc[ntl][0] * inv0, oacc[ntl][1] * inv0);
        *(float2*)(ctx + ((size_t)b * SQ + row0 + 8) * DM + col) =
            make_float2(oacc[ntl][2] * inv1, oacc[ntl][3] * inv1);
    }
}

// ---------------------------------------------------------------------------
// Launch
// ---------------------------------------------------------------------------
extern "C" void kernel_launch(void* const* d_in, const int* in_sizes, int n_in,
                              void* d_out, int out_size)
{
    const float* query = (const float*)d_in[0];
    const float* key   = (const float*)d_in[1];
    const float* value = (const float*)d_in[2];
    const float* Wq = (const float*)d_in[3];
    const float* bq = (const float*)d_in[4];
    const float* Wk = (const float*)d_in[5];
    const float* bk = (const float*)d_in[6];
    const float* Wv = (const float*)d_in[7];
    const float* bv = (const float*)d_in[8];
    const float* Wo = (const float*)d_in[9];
    const float* bo = (const float*)d_in[10];
    float* out = (float*)d_out;

    float *pQ, *pK, *pV, *pC;
    cudaGetSymbolAddress((void**)&pQ, g_Q);
    cudaGetSymbolAddress((void**)&pK, g_K);
    cudaGetSymbolAddress((void**)&pV, g_V);
    cudaGetSymbolAddress((void**)&pC, g_ctx);

    cudaFuncSetAttribute(attn3_kernel,
                         cudaFuncAttributeMaxDynamicSharedMemorySize,
                         ATTN_SMEM_BYTES);

    dim3 pg(DM / 128, MTOT / 128);   // (8, 32)
    proj4_kernel<1><<<pg, 256>>>(query, Wq, bq, pQ);
    proj4_kernel<1><<<pg, 256>>>(key,   Wk, bk, pK);
    proj4_kernel<1><<<pg, 256>>>(value, Wv, bv, pV);

    dim3 ag(BZ * NH, SQ / 128);      // (32, 16)
    attn3_kernel<<<ag, 256, ATTN_SMEM_BYTES>>>(pQ, pK, pV, pC);

    proj4_kernel<0><<<pg, 256>>>(pC, Wo, bo, out);
}

// round 10
// speedup vs baseline: 3.5121x; 2.1270x over previous
#include <cuda_runtime.h>
#include <cuda_bf16.h>
#include <cstdint>
#include <math.h>

// Problem constants (fixed by the reference).
#define BZ   2
#define SQ   2048
#define DM   1024
#define NH   16
#define HD   64
#define MTOT (BZ * SQ)   // 4096

// ---------------------------------------------------------------------------
// mma.sync / ldmatrix helpers (family-portable PTX: compiles for compute_103)
// ---------------------------------------------------------------------------
__device__ __forceinline__ uint32_t smem_u32(const void* p) {
    uint32_t a;
    asm("{ .reg .u64 t; cvta.to.shared.u64 t, %1; cvt.u32.u64 %0, t; }"
        : "=r"(a) : "l"(p));
    return a;
}

__device__ __forceinline__ void ldm4(uint32_t* r, uint32_t addr) {
    asm volatile("ldmatrix.sync.aligned.m8n8.x4.shared.b16 {%0,%1,%2,%3}, [%4];"
                 : "=r"(r[0]), "=r"(r[1]), "=r"(r[2]), "=r"(r[3]) : "r"(addr));
}
__device__ __forceinline__ void ldm4t(uint32_t* r, uint32_t addr) {
    asm volatile("ldmatrix.sync.aligned.m8n8.x4.trans.shared.b16 {%0,%1,%2,%3}, [%4];"
                 : "=r"(r[0]), "=r"(r[1]), "=r"(r[2]), "=r"(r[3]) : "r"(addr));
}

// d += a(bf16) * b(bf16), m16n8k16, fp32 accumulate
__device__ __forceinline__ void mma_bf16(float* d, const uint32_t* a,
                                         uint32_t b0, uint32_t b1) {
    asm volatile(
        "mma.sync.aligned.m16n8k16.row.col.f32.bf16.bf16.f32 "
        "{%0,%1,%2,%3}, {%4,%5,%6,%7}, {%8,%9}, {%0,%1,%2,%3};"
        : "+f"(d[0]), "+f"(d[1]), "+f"(d[2]), "+f"(d[3])
        : "r"(a[0]), "r"(a[1]), "r"(a[2]), "r"(a[3]), "r"(b0), "r"(b1));
}

// pack two floats -> bf16x2 (e0 in low half, e1 in high half)
__device__ __forceinline__ uint32_t pack2(float e0, float e1) {
    __nv_bfloat162 h = __floats2bfloat162_rn(e0, e1);   // x = e0 (low), y = e1
    return *reinterpret_cast<uint32_t*>(&h);
}
__device__ __forceinline__ float unpk_lo(uint32_t d) { return __uint_as_float(d << 16); }
__device__ __forceinline__ float unpk_hi(uint32_t d) { return __uint_as_float(d & 0xFFFF0000u); }

// split float4 into bf16 hi-plane (h) and lo-plane (l), 2 elems per word
__device__ __forceinline__ void split4f(float4 v, uint2& h, uint2& l) {
    uint32_t h0 = pack2(v.x, v.y);
    uint32_t h1 = pack2(v.z, v.w);
    float r0 = v.x - unpk_lo(h0), r1 = v.y - unpk_hi(h0);
    float r2 = v.z - unpk_lo(h1), r3 = v.w - unpk_hi(h1);
    h.x = h0; h.y = h1;
    l.x = pack2(r0, r1);
    l.y = pack2(r2, r3);
}

// ---------------------------------------------------------------------------
// Scratch (device globals: no allocation allowed in kernel_launch)
// ---------------------------------------------------------------------------
__device__ float g_Q[BZ * NH * SQ * HD];    // [B,H,S,Hd]
__device__ float g_K[BZ * NH * SQ * HD];
__device__ float g_V[BZ * NH * SQ * HD];
__device__ float g_ctx[BZ * SQ * DM];       // [B,S,D]

// ---------------------------------------------------------------------------
// proj5: bf16x3 mma.sync GEMM (split once at fill; inner loop pure LDSM+HMMA).
// Y[m,n] = sum_k X[m,k]W[n,k] + bias[n].  CTA tile 128x128, BK=32, 256 thr,
// 8 warps (2Mx4N), warp tile 64x32.  smem planes: Ahi/Alo/Bhi/Blo bf16,
// stride 40 elems (80B rows -> ldmatrix conflict-free).
// ---------------------------------------------------------------------------
#define PST 40      // bf16 elems per smem row
#define PBK 32

template <int HEAD_LAYOUT>
__global__ __launch_bounds__(256, 2)
void proj5_kernel(const float* __restrict__ X, const float* __restrict__ W,
                  const float* __restrict__ bias, float* __restrict__ Y)
{
    __shared__ unsigned short Ahi[128 * PST], Alo[128 * PST];
    __shared__ unsigned short Bhi[128 * PST], Blo[128 * PST];

    const int tid = threadIdx.x, lane = tid & 31, wid = tid >> 5;
    const int wm = wid & 1, wn = wid >> 1;
    const int mb_blk = blockIdx.y * 128, nb_blk = blockIdx.x * 128;

    const float* Xp = X + (size_t)mb_blk * DM;
    const float* Wp = W + (size_t)nb_blk * DM;

    int lrow[4], lcw[4];
#pragma unroll
    for (int j = 0; j < 4; j++) { int id = tid + 256 * j; lrow[j] = id >> 3; lcw[j] = (id & 7) * 4; }

    float4 xa[4], wb[4];
#pragma unroll
    for (int j = 0; j < 4; j++) {
        xa[j] = *(const float4*)(Xp + (size_t)lrow[j] * DM + lcw[j]);
        wb[j] = *(const float4*)(Wp + (size_t)lrow[j] * DM + lcw[j]);
    }

    float acc[4][4][4];
#pragma unroll
    for (int i = 0; i < 4; i++)
#pragma unroll
        for (int j = 0; j < 4; j++)
#pragma unroll
            for (int r = 0; r < 4; r++) acc[i][j][r] = 0.f;

    // ldmatrix byte offsets (row pitch = 80B)
    const uint32_t aAh = smem_u32(Ahi) + (64 * wm + (lane & 15)) * 80 + (lane >> 4) * 16;
    const uint32_t aAl = smem_u32(Alo) + (64 * wm + (lane & 15)) * 80 + (lane >> 4) * 16;
    const uint32_t bBh = smem_u32(Bhi) + (32 * wn + (lane & 7) + ((lane >> 4) << 3)) * 80
                         + (((lane >> 3) & 1)) * 16;
    const uint32_t bBl = smem_u32(Blo) + (32 * wn + (lane & 7) + ((lane >> 4) << 3)) * 80
                         + (((lane >> 3) & 1)) * 16;

    for (int kc = 0; kc < DM / PBK; kc++) {
        __syncthreads();
#pragma unroll
        for (int j = 0; j < 4; j++) {
            uint2 h, l;
            split4f(xa[j], h, l);
            *(uint2*)(Ahi + lrow[j] * PST + lcw[j]) = h;
            *(uint2*)(Alo + lrow[j] * PST + lcw[j]) = l;
            split4f(wb[j], h, l);
            *(uint2*)(Bhi + lrow[j] * PST + lcw[j]) = h;
            *(uint2*)(Blo + lrow[j] * PST + lcw[j]) = l;
        }
        __syncthreads();
        if (kc + 1 < DM / PBK) {
#pragma unroll
            for (int j = 0; j < 4; j++) {
                xa[j] = *(const float4*)(Xp + (size_t)lrow[j] * DM + (kc + 1) * PBK + lcw[j]);
                wb[j] = *(const float4*)(Wp + (size_t)lrow[j] * DM + (kc + 1) * PBK + lcw[j]);
            }
        }
#pragma unroll
        for (int ks = 0; ks < 2; ks++) {
            const uint32_t ko = ks * 32;        // 16 elems * 2B
            uint32_t bh0[4], bl0[4], bh1[4], bl1[4];
            ldm4(bh0, bBh + ko);                // n-tiles 0,1 (b0,b1 | b0,b1)
            ldm4(bl0, bBl + ko);
            ldm4(bh1, bBh + 1280 + ko);         // n-tiles 2,3 (16*80 = 1280)
            ldm4(bl1, bBl + 1280 + ko);
#pragma unroll
            for (int mt = 0; mt < 4; mt++) {
                uint32_t ah[4], al[4];
                ldm4(ah, aAh + mt * 1280 + ko);
                ldm4(al, aAl + mt * 1280 + ko);
                mma_bf16(acc[mt][0], ah, bh0[0], bh0[1]);
                mma_bf16(acc[mt][0], ah, bl0[0], bl0[1]);
                mma_bf16(acc[mt][0], al, bh0[0], bh0[1]);
                mma_bf16(acc[mt][1], ah, bh0[2], bh0[3]);
                mma_bf16(acc[mt][1], ah, bl0[2], bl0[3]);
                mma_bf16(acc[mt][1], al, bh0[2], bh0[3]);
                mma_bf16(acc[mt][2], ah, bh1[0], bh1[1]);
                mma_bf16(acc[mt][2], ah, bl1[0], bl1[1]);
                mma_bf16(acc[mt][2], al, bh1[0], bh1[1]);
                mma_bf16(acc[mt][3], ah, bh1[2], bh1[3]);
                mma_bf16(acc[mt][3], ah, bl1[2], bl1[3]);
                mma_bf16(acc[mt][3], al, bh1[2], bh1[3]);
            }
        }
    }

    // epilogue: D-frag rows g,g+8; cols 2t,2t+1
    const int g = lane >> 2, t = lane & 3;
#pragma unroll
    for (int mt = 0; mt < 4; mt++) {
#pragma unroll
        for (int nt = 0; nt < 4; nt++) {
            int n = nb_blk + 32 * wn + 8 * nt + 2 * t;
            float2 bv = *(const float2*)(bias + n);
            float v00 = acc[mt][nt][0] + bv.x, v01 = acc[mt][nt][1] + bv.y;
            float v10 = acc[mt][nt][2] + bv.x, v11 = acc[mt][nt][3] + bv.y;
            int m = mb_blk + 64 * wm + 16 * mt + g;
            if (HEAD_LAYOUT) {
                int b = m >> 11, s = m & (SQ - 1);
                int h = n >> 6, hd = n & 63;
                size_t base = (((size_t)b * NH + h) * SQ + s) * HD + hd;
                *(float2*)(Y + base) = make_float2(v00, v01);
                *(float2*)(Y + base + 8 * HD) = make_float2(v10, v11);
            } else {
                *(float2*)(Y + (size_t)m * DM + n) = make_float2(v00, v01);
                *(float2*)(Y + (size_t)(m + 8) * DM + n) = make_float2(v10, v11);
            }
        }
    }
}

// ---------------------------------------------------------------------------
// attn4: flash attention, bf16x3 mma.sync, FA2-style register P-fragments.
// CTA: 128 q-rows, key tiles of 64, 8 warps (warp w: rows 16w..16w+15).
// smem planes (bf16, row pitch 144B = 72 elems): Qhi/Qlo [128][64],
// Khi/Klo [64][64], Vhi/Vlo [64][64] (V in natural [key][hd]; ldmatrix.trans).
// No P smem round-trip: S accumulator frags convert in-register to A-frags.
// ---------------------------------------------------------------------------
#define AROWB 144
#define QHI_O 0
#define QLO_O (128 * AROWB)              // 18432
#define KHI_O (QLO_O + 128 * AROWB)      // 36864
#define KLO_O (KHI_O + 64 * AROWB)       // 46080
#define VHI_O (KLO_O + 64 * AROWB)       // 55296
#define VLO_O (VHI_O + 64 * AROWB)       // 64512
#define ATTN_SMEM_BYTES (VLO_O + 64 * AROWB)   // 73728

__global__ __launch_bounds__(256, 2)
void attn4_kernel(const float* __restrict__ Q, const float* __restrict__ K,
                  const float* __restrict__ V, float* __restrict__ ctx)
{
    extern __shared__ unsigned char smc[];
    const uint32_t sbase = smem_u32(smc);

    const int bh = blockIdx.x, m0 = blockIdx.y * 128;
    const int tid = threadIdx.x, lane = tid & 31, wid = tid >> 5;

    const float* Qb = Q + (size_t)bh * SQ * HD;
    const float* Kb = K + (size_t)bh * SQ * HD;
    const float* Vb = V + (size_t)bh * SQ * HD;

    // ---- load Q tile once: scale by 1/8, split to bf16 hi/lo planes ----
#pragma unroll
    for (int j = 0; j < 8; j++) {
        int id = tid + 256 * j;
        int row = id >> 4, c = (id & 15) * 4;
        float4 q = *(const float4*)(Qb + (size_t)(m0 + row) * HD + c);
        q.x *= 0.125f; q.y *= 0.125f; q.z *= 0.125f; q.w *= 0.125f;
        uint2 h, l;
        split4f(q, h, l);
        *(uint2*)(smc + QHI_O + row * AROWB + c * 2) = h;
        *(uint2*)(smc + QLO_O + row * AROWB + c * 2) = l;
    }

    // ldmatrix base addresses
    const uint32_t qa = sbase + QHI_O + (16 * wid + (lane & 15)) * AROWB + (lane >> 4) * 16;
    const uint32_t kb = sbase + KHI_O + ((lane & 7) + ((lane >> 4) << 3)) * AROWB
                        + ((lane >> 3) & 1) * 16;
    const uint32_t vb = sbase + VHI_O + ((lane & 7) + ((lane >> 3) & 1) * 8) * AROWB
                        + (lane >> 4) * 16;

    float oacc[8][4];
#pragma unroll
    for (int i = 0; i < 8; i++)
#pragma unroll
        for (int r = 0; r < 4; r++) oacc[i][r] = 0.f;
    float mi[2] = {-1e30f, -1e30f}, li[2] = {0.f, 0.f};

    for (int kt0 = 0; kt0 < SQ; kt0 += 64) {
        __syncthreads();
        // ---- fill K and V planes (split at fill) ----
#pragma unroll
        for (int j = 0; j < 4; j++) {
            int id = tid + 256 * j;
            int row = id >> 4, c = (id & 15) * 4;
            float4 kv = *(const float4*)(Kb + (size_t)(kt0 + row) * HD + c);
            uint2 h, l;
            split4f(kv, h, l);
            *(uint2*)(smc + KHI_O + row * AROWB + c * 2) = h;
            *(uint2*)(smc + KLO_O + row * AROWB + c * 2) = l;
            float4 vv = *(const float4*)(Vb + (size_t)(kt0 + row) * HD + c);
            split4f(vv, h, l);
            *(uint2*)(smc + VHI_O + row * AROWB + c * 2) = h;
            *(uint2*)(smc + VLO_O + row * AROWB + c * 2) = l;
        }
        __syncthreads();

        // ---- QK^T: S[16 x 64] per warp, bf16x3 ----
        float sacc[8][4];
#pragma unroll
        for (int i = 0; i < 8; i++)
#pragma unroll
            for (int r = 0; r < 4; r++) sacc[i][r] = 0.f;

#pragma unroll
        for (int ks = 0; ks < 4; ks++) {
            const uint32_t ko = ks * 32;
            uint32_t qh[4], ql[4];
            ldm4(qh, qa + ko);
            ldm4(ql, qa + (QLO_O - QHI_O) + ko);
#pragma unroll
            for (int kg = 0; kg < 4; kg++) {
                uint32_t kh[4], kl[4];
                ldm4(kh, kb + kg * (16 * AROWB) + ko);
                ldm4(kl, kb + (KLO_O - KHI_O) + kg * (16 * AROWB) + ko);
                mma_bf16(sacc[2 * kg],     qh, kh[0], kh[1]);
                mma_bf16(sacc[2 * kg],     qh, kl[0], kl[1]);
                mma_bf16(sacc[2 * kg],     ql, kh[0], kh[1]);
                mma_bf16(sacc[2 * kg + 1], qh, kh[2], kh[3]);
                mma_bf16(sacc[2 * kg + 1], qh, kl[2], kl[3]);
                mma_bf16(sacc[2 * kg + 1], ql, kh[2], kh[3]);
            }
        }

        // ---- online softmax (rows g, g+8; quad-wide reductions) ----
        float mx0 = -1e30f, mx1 = -1e30f;
#pragma unroll
        for (int ntl = 0; ntl < 8; ntl++) {
            mx0 = fmaxf(mx0, fmaxf(sacc[ntl][0], sacc[ntl][1]));
            mx1 = fmaxf(mx1, fmaxf(sacc[ntl][2], sacc[ntl][3]));
        }
#pragma unroll
        for (int o = 1; o < 4; o <<= 1) {
            mx0 = fmaxf(mx0, __shfl_xor_sync(0xffffffffu, mx0, o, 4));
            mx1 = fmaxf(mx1, __shfl_xor_sync(0xffffffffu, mx1, o, 4));
        }
        float mn0 = fmaxf(mi[0], mx0), mn1 = fmaxf(mi[1], mx1);
        float corr0 = __expf(mi[0] - mn0), corr1 = __expf(mi[1] - mn1);
        mi[0] = mn0; mi[1] = mn1;
        float rs0 = 0.f, rs1 = 0.f;
#pragma unroll
        for (int ntl = 0; ntl < 8; ntl++) {
            sacc[ntl][0] = __expf(sacc[ntl][0] - mn0); rs0 += sacc[ntl][0];
            sacc[ntl][1] = __expf(sacc[ntl][1] - mn0); rs0 += sacc[ntl][1];
            sacc[ntl][2] = __expf(sacc[ntl][2] - mn1); rs1 += sacc[ntl][2];
            sacc[ntl][3] = __expf(sacc[ntl][3] - mn1); rs1 += sacc[ntl][3];
        }
#pragma unroll
        for (int o = 1; o < 4; o <<= 1) {
            rs0 += __shfl_xor_sync(0xffffffffu, rs0, o, 4);
            rs1 += __shfl_xor_sync(0xffffffffu, rs1, o, 4);
        }
        li[0] = li[0] * corr0 + rs0;
        li[1] = li[1] * corr1 + rs1;
#pragma unroll
        for (int ntl = 0; ntl < 8; ntl++) {
            oacc[ntl][0] *= corr0; oacc[ntl][1] *= corr0;
            oacc[ntl][2] *= corr1; oacc[ntl][3] *= corr1;
        }

        // ---- PV: O[16 x 64] += P * V ; P a-frags built in registers ----
#pragma unroll
        for (int s = 0; s < 4; s++) {
            const float* p0 = sacc[2 * s];
            const float* p1 = sacc[2 * s + 1];
            uint32_t ah[4], al[4];
            ah[0] = pack2(p0[0], p0[1]);
            ah[1] = pack2(p0[2], p0[3]);
            ah[2] = pack2(p1[0], p1[1]);
            ah[3] = pack2(p1[2], p1[3]);
            al[0] = pack2(p0[0] - unpk_lo(ah[0]), p0[1] - unpk_hi(ah[0]));
            al[1] = pack2(p0[2] - unpk_lo(ah[1]), p0[3] - unpk_hi(ah[1]));
            al[2] = pack2(p1[0] - unpk_lo(ah[2]), p1[1] - unpk_hi(ah[2]));
            al[3] = pack2(p1[2] - unpk_lo(ah[3]), p1[3] - unpk_hi(ah[3]));
#pragma unroll
            for (int ng = 0; ng < 4; ng++) {
                uint32_t vh[4], vl[4];
                ldm4t(vh, vb + s * (16 * AROWB) + ng * 32);
                ldm4t(vl, vb + (VLO_O - VHI_O) + s * (16 * AROWB) + ng * 32);
                mma_bf16(oacc[2 * ng],     ah, vh[0], vh[1]);
                mma_bf16(oacc[2 * ng],     ah, vl[0], vl[1]);
                mma_bf16(oacc[2 * ng],     al, vh[0], vh[1]);
                mma_bf16(oacc[2 * ng + 1], ah, vh[2], vh[3]);
                mma_bf16(oacc[2 * ng + 1], ah, vl[2], vl[3]);
                mma_bf16(oacc[2 * ng + 1], al, vh[2], vh[3]);
            }
        }
    }

    // ---- normalize + write ctx [B,S,D] ----
    const int g = lane >> 2, t = lane & 3;
    const int b = bh >> 4, h = bh & 15;
    const float inv0 = 1.f / li[0], inv1 = 1.f / li[1];
    const int row0 = m0 + 16 * wid + g;
#pragma unroll
    for (int ntl = 0; ntl < 8; ntl++) {
        int col = h * HD + 8 * ntl + 2 * t;
        *(float2*)(ctx + ((size_t)b * SQ + row0) * DM + col) =
            make_float2(oacc[ntl][0] * inv0, oacc[ntl][1] * inv0);
        *(float2*)(ctx + ((size_t)b * SQ + row0 + 8) * DM + col) =
            make_float2(oacc[ntl][2] * inv1, oacc[ntl][3] * inv1);
    }
}

// ---------------------------------------------------------------------------
// Launch
// ---------------------------------------------------------------------------
extern "C" void kernel_launch(void* const* d_in, const int* in_sizes, int n_in,
                              void* d_out, int out_size)
{
    const float* query = (const float*)d_in[0];
    const float* key   = (const float*)d_in[1];
    const float* value = (const float*)d_in[2];
    const float* Wq = (const float*)d_in[3];
    const float* bq = (const float*)d_in[4];
    const float* Wk = (const float*)d_in[5];
    const float* bk = (const float*)d_in[6];
    const float* Wv = (const float*)d_in[7];
    const float* bv = (const float*)d_in[8];
    const float* Wo = (const float*)d_in[9];
    const float* bo = (const float*)d_in[10];
    float* out = (float*)d_out;

    float *pQ, *pK, *pV, *pC;
    cudaGetSymbolAddress((void**)&pQ, g_Q);
    cudaGetSymbolAddress((void**)&pK, g_K);
    cudaGetSymbolAddress((void**)&pV, g_V);
    cudaGetSymbolAddress((void**)&pC, g_ctx);

    cudaFuncSetAttribute(attn4_kernel,
                         cudaFuncAttributeMaxDynamicSharedMemorySize,
                         ATTN_SMEM_BYTES);

    dim3 pg(DM / 128, MTOT / 128);   // (8, 32)
    proj5_kernel<1><<<pg, 256>>>(query, Wq, bq, pQ);
    proj5_kernel<1><<<pg, 256>>>(key,   Wk, bk, pK);
    proj5_kernel<1><<<pg, 256>>>(value, Wv, bv, pV);

    dim3 ag(BZ * NH, SQ / 128);      // (32, 16)
    attn4_kernel<<<ag, 256, ATTN_SMEM_BYTES>>>(pQ, pK, pV, pC);

    proj5_kernel<0><<<pg, 256>>>(pC, Wo, bo, out);
}

// round 13
// speedup vs baseline: 3.5669x; 1.0156x over previous
#include <cuda_runtime.h>
#include <cuda_bf16.h>
#include <cstdint>
#include <math.h>

// Problem constants (fixed by the reference).
#define BZ   2
#define SQ   2048
#define DM   1024
#define NH   16
#define HD   64
#define MTOT (BZ * SQ)   // 4096

typedef unsigned short us16;

// ---------------------------------------------------------------------------
// mma.sync / ldmatrix / cp.async helpers (family-portable: compute_103-safe)
// ---------------------------------------------------------------------------
__device__ __forceinline__ uint32_t smem_u32(const void* p) {
    uint32_t a;
    asm("{ .reg .u64 t; cvta.to.shared.u64 t, %1; cvt.u32.u64 %0, t; }"
        : "=r"(a) : "l"(p));
    return a;
}
__device__ __forceinline__ void ldm4(uint32_t* r, uint32_t addr) {
    asm volatile("ldmatrix.sync.aligned.m8n8.x4.shared.b16 {%0,%1,%2,%3}, [%4];"
                 : "=r"(r[0]), "=r"(r[1]), "=r"(r[2]), "=r"(r[3]) : "r"(addr));
}
__device__ __forceinline__ void ldm4t(uint32_t* r, uint32_t addr) {
    asm volatile("ldmatrix.sync.aligned.m8n8.x4.trans.shared.b16 {%0,%1,%2,%3}, [%4];"
                 : "=r"(r[0]), "=r"(r[1]), "=r"(r[2]), "=r"(r[3]) : "r"(addr));
}
__device__ __forceinline__ void mma_bf16(float* d, const uint32_t* a,
                                         uint32_t b0, uint32_t b1) {
    asm volatile(
        "mma.sync.aligned.m16n8k16.row.col.f32.bf16.bf16.f32 "
        "{%0,%1,%2,%3}, {%4,%5,%6,%7}, {%8,%9}, {%0,%1,%2,%3};"
        : "+f"(d[0]), "+f"(d[1]), "+f"(d[2]), "+f"(d[3])
        : "r"(a[0]), "r"(a[1]), "r"(a[2]), "r"(a[3]), "r"(b0), "r"(b1));
}
__device__ __forceinline__ void cp16(uint32_t dst, const void* src) {
    asm volatile("cp.async.cg.shared.global [%0], [%1], 16;" :: "r"(dst), "l"(src));
}
#define CP_COMMIT() asm volatile("cp.async.commit_group;" ::: "memory")
#define CP_WAIT1()  asm volatile("cp.async.wait_group 1;" ::: "memory")

__device__ __forceinline__ uint32_t pack2(float e0, float e1) {
    __nv_bfloat162 h = __floats2bfloat162_rn(e0, e1);
    return *reinterpret_cast<uint32_t*>(&h);
}
__device__ __forceinline__ float unpk_lo(uint32_t d) { return __uint_as_float(d << 16); }
__device__ __forceinline__ float unpk_hi(uint32_t d) { return __uint_as_float(d & 0xFFFF0000u); }

__device__ __forceinline__ void split4f(float4 v, uint2& h, uint2& l) {
    uint32_t h0 = pack2(v.x, v.y);
    uint32_t h1 = pack2(v.z, v.w);
    h.x = h0; h.y = h1;
    l.x = pack2(v.x - unpk_lo(h0), v.y - unpk_hi(h0));
    l.y = pack2(v.z - unpk_lo(h1), v.w - unpk_hi(h1));
}

// ---------------------------------------------------------------------------
// Scratch (device globals; ~134MB of bf16 planes)
// ---------------------------------------------------------------------------
#define NXD (MTOT * DM)    // 4194304
#define NWD (DM * DM)      // 1048576
__device__ us16 gXq_h[NXD], gXq_l[NXD];
__device__ us16 gXk_h[NXD], gXk_l[NXD];
__device__ us16 gXv_h[NXD], gXv_l[NXD];
__device__ us16 gWq_h[NWD], gWq_l[NWD];
__device__ us16 gWk_h[NWD], gWk_l[NWD];
__device__ us16 gWv_h[NWD], gWv_l[NWD];
__device__ us16 gWo_h[NWD], gWo_l[NWD];
__device__ us16 gQh[NXD], gQl[NXD];     // [B,H,S,Hd]
__device__ us16 gKh[NXD], gKl[NXD];
__device__ us16 gVh[NXD], gVl[NXD];
__device__ us16 gCh[NXD], gCl[NXD];     // ctx [B,S,D]

// ---------------------------------------------------------------------------
// prep: split fp32 tensor into bf16 hi/lo planes
// ---------------------------------------------------------------------------
__global__ void split_kernel(const float* __restrict__ x,
                             us16* __restrict__ h, us16* __restrict__ l, int n4)
{
    int i = blockIdx.x * blockDim.x + threadIdx.x;
    if (i >= n4) return;
    float4 v = ((const float4*)x)[i];
    uint2 hh, ll;
    split4f(v, hh, ll);
    ((uint2*)h)[i] = hh;
    ((uint2*)l)[i] = ll;
}

// ---------------------------------------------------------------------------
// proj6: bf16x3 GEMM, pre-split A/B planes, cp.async 2-stage double buffer.
// Y[m,n] = (sum_k A[m,k]B[n,k] + bias[n]) * scale.
// CTA 128x128, BK=32, 256 thr, 8 warps (2Mx4N), inner loop pure LDSM+HMMA.
// smem: 2 stages x 4 planes x (128 rows x 80B) = 80KB dynamic.
// HEAD_LAYOUT=1: write split planes to [B,H,S,Hd]; =0: fp32 row-major.
// ---------------------------------------------------------------------------
#define PPLANE 10240                  // 128*80
#define PSTAGE (4 * PPLANE)           // 40960
#define PROJ_SMEM (2 * PSTAGE)        // 81920

template <int HEAD_LAYOUT>
__global__ __launch_bounds__(256, 2)
void proj6_kernel(const us16* __restrict__ Ah_g, const us16* __restrict__ Al_g,
                  const us16* __restrict__ Bh_g, const us16* __restrict__ Bl_g,
                  const float* __restrict__ bias, float scale,
                  us16* __restrict__ Yh, us16* __restrict__ Yl,
                  float* __restrict__ Yf)
{
    extern __shared__ unsigned char psm[];
    const uint32_t sbase = smem_u32(psm);

    const int tid = threadIdx.x, lane = tid & 31, wid = tid >> 5;
    const int wm = wid & 1, wn = wid >> 1;
    const int mb = blockIdx.y * 128, nb = blockIdx.x * 128;

    const us16* srcs[4] = {Ah_g + (size_t)mb * DM, Al_g + (size_t)mb * DM,
                           Bh_g + (size_t)nb * DM, Bl_g + (size_t)nb * DM};

    // fill one stage: 2048 chunks of 16B (A hi/lo + B hi/lo)
    auto fill = [&](int kc, int buf) {
#pragma unroll
        for (int j = 0; j < 8; j++) {
            int sel = j >> 1;
            int cc = tid + 256 * (j & 1);
            int row = cc >> 2, ch = tid & 3;
            cp16(sbase + buf * PSTAGE + sel * PPLANE + row * 80 + ch * 16,
                 srcs[sel] + (size_t)row * DM + kc * 32 + ch * 8);
        }
    };

    fill(0, 0); CP_COMMIT();
    fill(1, 1); CP_COMMIT();

    float acc[4][4][4];
#pragma unroll
    for (int i = 0; i < 4; i++)
#pragma unroll
        for (int j = 0; j < 4; j++)
#pragma unroll
            for (int r = 0; r < 4; r++) acc[i][j][r] = 0.f;

    // lane-constant parts of ldmatrix addresses (row pitch 80B)
    const uint32_t aL = (64 * wm + (lane & 15)) * 80 + (lane >> 4) * 16;
    const uint32_t bL = (32 * wn + (lane & 7) + ((lane >> 4) << 3)) * 80
                        + ((lane >> 3) & 1) * 16;

    for (int kc = 0; kc < DM / 32; kc++) {
        CP_WAIT1();
        __syncthreads();
        const uint32_t so = (kc & 1) * PSTAGE;
        const uint32_t aAh = sbase + so + aL;
        const uint32_t bBh = sbase + so + 2 * PPLANE + bL;
#pragma unroll
        for (int ks = 0; ks < 2; ks++) {
            const uint32_t ko = ks * 32;
            uint32_t bh0[4], bl0[4], bh1[4], bl1[4];
            ldm4(bh0, bBh + ko);
            ldm4(bl0, bBh + PPLANE + ko);
            ldm4(bh1, bBh + 1280 + ko);
            ldm4(bl1, bBh + PPLANE + 1280 + ko);
#pragma unroll
            for (int mt = 0; mt < 4; mt++) {
                uint32_t ah[4], al[4];
                ldm4(ah, aAh + mt * 1280 + ko);
                ldm4(al, aAh + PPLANE + mt * 1280 + ko);
                mma_bf16(acc[mt][0], ah, bh0[0], bh0[1]);
                mma_bf16(acc[mt][0], ah, bl0[0], bl0[1]);
                mma_bf16(acc[mt][0], al, bh0[0], bh0[1]);
                mma_bf16(acc[mt][1], ah, bh0[2], bh0[3]);
                mma_bf16(acc[mt][1], ah, bl0[2], bl0[3]);
                mma_bf16(acc[mt][1], al, bh0[2], bh0[3]);
                mma_bf16(acc[mt][2], ah, bh1[0], bh1[1]);
                mma_bf16(acc[mt][2], ah, bl1[0], bl1[1]);
                mma_bf16(acc[mt][2], al, bh1[0], bh1[1]);
                mma_bf16(acc[mt][3], ah, bh1[2], bh1[3]);
                mma_bf16(acc[mt][3], ah, bl1[2], bl1[3]);
                mma_bf16(acc[mt][3], al, bh1[2], bh1[3]);
            }
        }
        __syncthreads();
        if (kc + 2 < DM / 32) fill(kc + 2, kc & 1);
        CP_COMMIT();
    }

    // epilogue
    const int g = lane >> 2, t = lane & 3;
#pragma unroll
    for (int mt = 0; mt < 4; mt++) {
#pragma unroll
        for (int nt = 0; nt < 4; nt++) {
            int n = nb + 32 * wn + 8 * nt + 2 * t;
            float2 bv = *(const float2*)(bias + n);
            float v00 = (acc[mt][nt][0] + bv.x) * scale;
            float v01 = (acc[mt][nt][1] + bv.y) * scale;
            float v10 = (acc[mt][nt][2] + bv.x) * scale;
            float v11 = (acc[mt][nt][3] + bv.y) * scale;
            int m = mb + 64 * wm + 16 * mt + g;
            if (HEAD_LAYOUT) {
                int b = m >> 11, s = m & (SQ - 1);
                int h = n >> 6, hd = n & 63;
                size_t base = (((size_t)b * NH + h) * SQ + s) * HD + hd;
                uint32_t h0 = pack2(v00, v01);
                uint32_t l0 = pack2(v00 - unpk_lo(h0), v01 - unpk_hi(h0));
                uint32_t h1 = pack2(v10, v11);
                uint32_t l1 = pack2(v10 - unpk_lo(h1), v11 - unpk_hi(h1));
                *(uint32_t*)(Yh + base) = h0;
                *(uint32_t*)(Yl + base) = l0;
                *(uint32_t*)(Yh + base + 8 * HD) = h1;
                *(uint32_t*)(Yl + base + 8 * HD) = l1;
            } else {
                *(float2*)(Yf + (size_t)m * DM + n) = make_float2(v00, v01);
                *(float2*)(Yf + (size_t)(m + 8) * DM + n) = make_float2(v10, v11);
            }
        }
    }
}

// ---------------------------------------------------------------------------
// attn5: flash attention, bf16x3 mma.sync, pre-split Q/K/V planes, cp.async
// double-buffered K/V. CTA: 128 q-rows, 64-key tiles, 8 warps.
// smem: KV 2 stages x 4 planes x (64 x 144B) + Q 2 planes x (128 x 144B)
//     = 73728 + 36864 = 110592 B (2 CTAs/SM -> 216KB).
// P fragments built in registers (FA2); ctx written as split planes.
// ---------------------------------------------------------------------------
#define KVPL 9216                 // 64*144
#define KVSTAGE (4 * KVPL)        // 36864
#define AQH_O (2 * KVSTAGE)       // 73728
#define AQL_O (AQH_O + 18432)     // 92160
#define ATTN_SMEM (AQL_O + 18432) // 110592

__global__ __launch_bounds__(256, 2)
void attn5_kernel(const us16* __restrict__ Qh_g, const us16* __restrict__ Ql_g,
                  const us16* __restrict__ Kh_g, const us16* __restrict__ Kl_g,
                  const us16* __restrict__ Vh_g, const us16* __restrict__ Vl_g,
                  us16* __restrict__ Ch, us16* __restrict__ Cl)
{
    extern __shared__ unsigned char smc[];
    const uint32_t sbase = smem_u32(smc);

    const int bh = blockIdx.x, m0 = blockIdx.y * 128;
    const int tid = threadIdx.x, lane = tid & 31, wid = tid >> 5;
    const size_t bho = (size_t)bh * SQ * HD;

    const us16* kvsrc[4] = {Kh_g + bho, Kl_g + bho, Vh_g + bho, Vl_g + bho};
    const us16* qsrc[2] = {Qh_g + bho, Ql_g + bho};

    auto fill_kv = [&](int kt0, int buf) {
#pragma unroll
        for (int j = 0; j < 8; j++) {
            int pl = j >> 1;
            int cc = tid + 256 * (j & 1);
            int row = cc >> 3, ch = tid & 7;
            cp16(sbase + buf * KVSTAGE + pl * KVPL + row * 144 + ch * 16,
                 kvsrc[pl] + (size_t)(kt0 + row) * HD + ch * 8);
        }
    };

    // prologue: Q planes + KV stage 0 in group 0; KV stage 1 in group 1
#pragma unroll
    for (int j = 0; j < 8; j++) {
        int pl = j >> 2;
        int cc = tid + 256 * (j & 3);
        int row = cc >> 3, ch = tid & 7;
        cp16(sbase + AQH_O + pl * 18432 + row * 144 + ch * 16,
             qsrc[pl] + (size_t)(m0 + row) * HD + ch * 8);
    }
    fill_kv(0, 0);
    CP_COMMIT();
    fill_kv(64, 1);
    CP_COMMIT();

    // lane-constant ldmatrix address parts (row pitch 144B)
    const uint32_t qa = sbase + AQH_O + (16 * wid + (lane & 15)) * 144 + (lane >> 4) * 16;
    const uint32_t kbL = ((lane & 7) + ((lane >> 4) << 3)) * 144 + ((lane >> 3) & 1) * 16;
    const uint32_t vbL = ((lane & 7) + ((lane >> 3) & 1) * 8) * 144 + (lane >> 4) * 16;

    float oacc[8][4];
#pragma unroll
    for (int i = 0; i < 8; i++)
#pragma unroll
        for (int r = 0; r < 4; r++) oacc[i][r] = 0.f;
    float mi[2] = {-1e30f, -1e30f}, li[2] = {0.f, 0.f};

    const int NT = SQ / 64;
    for (int kt = 0; kt < NT; kt++) {
        CP_WAIT1();
        __syncthreads();
        const uint32_t so = (kt & 1) * KVSTAGE;
        const uint32_t kb = sbase + so + kbL;             // Khi; +KVPL = Klo
        const uint32_t vb = sbase + so + 2 * KVPL + vbL;  // Vhi; +KVPL = Vlo

        // ---- QK^T: S[16 x 64] per warp ----
        float sacc[8][4];
#pragma unroll
        for (int i = 0; i < 8; i++)
#pragma unroll
            for (int r = 0; r < 4; r++) sacc[i][r] = 0.f;

#pragma unroll
        for (int ks = 0; ks < 4; ks++) {
            const uint32_t ko = ks * 32;
            uint32_t qh[4], ql[4];
            ldm4(qh, qa + ko);
            ldm4(ql, qa + 18432 + ko);
#pragma unroll
            for (int kg = 0; kg < 4; kg++) {
                uint32_t kh[4], kl[4];
                ldm4(kh, kb + kg * (16 * 144) + ko);
                ldm4(kl, kb + KVPL + kg * (16 * 144) + ko);
                mma_bf16(sacc[2 * kg],     qh, kh[0], kh[1]);
                mma_bf16(sacc[2 * kg],     qh, kl[0], kl[1]);
                mma_bf16(sacc[2 * kg],     ql, kh[0], kh[1]);
                mma_bf16(sacc[2 * kg + 1], qh, kh[2], kh[3]);
                mma_bf16(sacc[2 * kg + 1], qh, kl[2], kl[3]);
                mma_bf16(sacc[2 * kg + 1], ql, kh[2], kh[3]);
            }
        }

        // ---- online softmax (rows g, g+8; quad-wide reductions) ----
        float mx0 = -1e30f, mx1 = -1e30f;
#pragma unroll
        for (int ntl = 0; ntl < 8; ntl++) {
            mx0 = fmaxf(mx0, fmaxf(sacc[ntl][0], sacc[ntl][1]));
            mx1 = fmaxf(mx1, fmaxf(sacc[ntl][2], sacc[ntl][3]));
        }
#pragma unroll
        for (int o = 1; o < 4; o <<= 1) {
            mx0 = fmaxf(mx0, __shfl_xor_sync(0xffffffffu, mx0, o, 4));
            mx1 = fmaxf(mx1, __shfl_xor_sync(0xffffffffu, mx1, o, 4));
        }
        float mn0 = fmaxf(mi[0], mx0), mn1 = fmaxf(mi[1], mx1);
        float corr0 = __expf(mi[0] - mn0), corr1 = __expf(mi[1] - mn1);
        mi[0] = mn0; mi[1] = mn1;
        float rs0 = 0.f, rs1 = 0.f;
#pragma unroll
        for (int ntl = 0; ntl < 8; ntl++) {
            sacc[ntl][0] = __expf(sacc[ntl][0] - mn0); rs0 += sacc[ntl][0];
            sacc[ntl][1] = __expf(sacc[ntl][1] - mn0); rs0 += sacc[ntl][1];
            sacc[ntl][2] = __expf(sacc[ntl][2] - mn1); rs1 += sacc[ntl][2];
            sacc[ntl][3] = __expf(sacc[ntl][3] - mn1); rs1 += sacc[ntl][3];
        }
#pragma unroll
        for (int o = 1; o < 4; o <<= 1) {
            rs0 += __shfl_xor_sync(0xffffffffu, rs0, o, 4);
            rs1 += __shfl_xor_sync(0xffffffffu, rs1, o, 4);
        }
        li[0] = li[0] * corr0 + rs0;
        li[1] = li[1] * corr1 + rs1;
#pragma unroll
        for (int ntl = 0; ntl < 8; ntl++) {
            oacc[ntl][0] *= corr0; oacc[ntl][1] *= corr0;
            oacc[ntl][2] *= corr1; oacc[ntl][3] *= corr1;
        }

        // ---- PV: O += P * V ; P a-frags built in registers ----
#pragma unroll
        for (int s = 0; s < 4; s++) {
            const float* p0 = sacc[2 * s];
            const float* p1 = sacc[2 * s + 1];
            uint32_t ah[4], al[4];
            ah[0] = pack2(p0[0], p0[1]);
            ah[1] = pack2(p0[2], p0[3]);
            ah[2] = pack2(p1[0], p1[1]);
            ah[3] = pack2(p1[2], p1[3]);
            al[0] = pack2(p0[0] - unpk_lo(ah[0]), p0[1] - unpk_hi(ah[0]));
            al[1] = pack2(p0[2] - unpk_lo(ah[1]), p0[3] - unpk_hi(ah[1]));
            al[2] = pack2(p1[0] - unpk_lo(ah[2]), p1[1] - unpk_hi(ah[2]));
            al[3] = pack2(p1[2] - unpk_lo(ah[3]), p1[3] - unpk_hi(ah[3]));
#pragma unroll
            for (int ng = 0; ng < 4; ng++) {
                uint32_t vh[4], vl[4];
                ldm4t(vh, vb + s * (16 * 144) + ng * 32);
                ldm4t(vl, vb + KVPL + s * (16 * 144) + ng * 32);
                mma_bf16(oacc[2 * ng],     ah, vh[0], vh[1]);
                mma_bf16(oacc[2 * ng],     ah, vl[0], vl[1]);
                mma_bf16(oacc[2 * ng],     al, vh[0], vh[1]);
                mma_bf16(oacc[2 * ng + 1], ah, vh[2], vh[3]);
                mma_bf16(oacc[2 * ng + 1], ah, vl[2], vl[3]);
                mma_bf16(oacc[2 * ng + 1], al, vh[2], vh[3]);
            }
        }

        __syncthreads();
        if (kt + 2 < NT) fill_kv((kt + 2) * 64, kt & 1);
        CP_COMMIT();
    }

    // ---- normalize + write ctx planes [B,S,D] ----
    const int g = lane >> 2, t = lane & 3;
    const int b = bh >> 4, h = bh & 15;
    const float inv0 = 1.f / li[0], inv1 = 1.f / li[1];
    const int row0 = m0 + 16 * wid + g;
#pragma unroll
    for (int ntl = 0; ntl < 8; ntl++) {
        int col = h * HD + 8 * ntl + 2 * t;
        size_t i0 = ((size_t)b * SQ + row0) * DM + col;
        size_t i1 = ((size_t)b * SQ + row0 + 8) * DM + col;
        float v0 = oacc[ntl][0] * inv0, v1 = oacc[ntl][1] * inv0;
        uint32_t h0 = pack2(v0, v1);
        *(uint32_t*)(Ch + i0) = h0;
        *(uint32_t*)(Cl + i0) = pack2(v0 - unpk_lo(h0), v1 - unpk_hi(h0));
        float v2 = oacc[ntl][2] * inv1, v3 = oacc[ntl][3] * inv1;
        uint32_t h1 = pack2(v2, v3);
        *(uint32_t*)(Ch + i1) = h1;
        *(uint32_t*)(Cl + i1) = pack2(v2 - unpk_lo(h1), v3 - unpk_hi(h1));
    }
}

// ---------------------------------------------------------------------------
// Launch
// ---------------------------------------------------------------------------
#define SYMADDR(var, sym) us16* var; cudaGetSymbolAddress((void**)&var, sym)

extern "C" void kernel_launch(void* const* d_in, const int* in_sizes, int n_in,
                              void* d_out, int out_size)
{
    const float* query = (const float*)d_in[0];
    const float* key   = (const float*)d_in[1];
    const float* value = (const float*)d_in[2];
    const float* Wq = (const float*)d_in[3];
    const float* bq = (const float*)d_in[4];
    const float* Wk = (const float*)d_in[5];
    const float* bk = (const float*)d_in[6];
    const float* Wv = (const float*)d_in[7];
    const float* bv = (const float*)d_in[8];
    const float* Wo = (const float*)d_in[9];
    const float* bo = (const float*)d_in[10];
    float* out = (float*)d_out;

    SYMADDR(xqh, gXq_h); SYMADDR(xql, gXq_l);
    SYMADDR(xkh, gXk_h); SYMADDR(xkl, gXk_l);
    SYMADDR(xvh, gXv_h); SYMADDR(xvl, gXv_l);
    SYMADDR(wqh, gWq_h); SYMADDR(wql, gWq_l);
    SYMADDR(wkh, gWk_h); SYMADDR(wkl, gWk_l);
    SYMADDR(wvh, gWv_h); SYMADDR(wvl, gWv_l);
    SYMADDR(woh, gWo_h); SYMADDR(wol, gWo_l);
    SYMADDR(qh, gQh); SYMADDR(ql, gQl);
    SYMADDR(kh, gKh); SYMADDR(kl, gKl);
    SYMADDR(vh, gVh); SYMADDR(vl, gVl);
    SYMADDR(ch, gCh); SYMADDR(cl, gCl);

    cudaFuncSetAttribute(attn5_kernel,
                         cudaFuncAttributeMaxDynamicSharedMemorySize, ATTN_SMEM);
    cudaFuncSetAttribute(proj6_kernel<1>,
                         cudaFuncAttributeMaxDynamicSharedMemorySize, PROJ_SMEM);
    cudaFuncSetAttribute(proj6_kernel<0>,
                         cudaFuncAttributeMaxDynamicSharedMemorySize, PROJ_SMEM);

    // 1) split inputs + weights into bf16 planes
    const int NX4 = NXD / 4, NW4 = NWD / 4;
    split_kernel<<<NX4 / 256, 256>>>(query, xqh, xql, NX4);
    split_kernel<<<NX4 / 256, 256>>>(key,   xkh, xkl, NX4);
    split_kernel<<<NX4 / 256, 256>>>(value, xvh, xvl, NX4);
    split_kernel<<<NW4 / 256, 256>>>(Wq, wqh, wql, NW4);
    split_kernel<<<NW4 / 256, 256>>>(Wk, wkh, wkl, NW4);
    split_kernel<<<NW4 / 256, 256>>>(Wv, wvh, wvl, NW4);
    split_kernel<<<NW4 / 256, 256>>>(Wo, woh, wol, NW4);

    // 2) projections (Q scaled by 1/sqrt(Hd) = 0.125)
    dim3 pg(DM / 128, MTOT / 128);   // (8, 32)
    proj6_kernel<1><<<pg, 256, PROJ_SMEM>>>(xqh, xql, wqh, wql, bq, 0.125f, qh, ql, nullptr);
    proj6_kernel<1><<<pg, 256, PROJ_SMEM>>>(xkh, xkl, wkh, wkl, bk, 1.0f,   kh, kl, nullptr);
    proj6_kernel<1><<<pg, 256, PROJ_SMEM>>>(xvh, xvl, wvh, wvl, bv, 1.0f,   vh, vl, nullptr);

    // 3) attention
    dim3 ag(BZ * NH, SQ / 128);      // (32, 16)
    attn5_kernel<<<ag, 256, ATTN_SMEM>>>(qh, ql, kh, kl, vh, vl, ch, cl);

    // 4) output projection (fp32 out)
    proj6_kernel<0><<<pg, 256, PROJ_SMEM>>>(ch, cl, woh, wol, bo, 1.0f,
                                            nullptr, nullptr, out);
}